// round 1
// baseline (speedup 1.0000x reference)
#include <cuda_runtime.h>
#include <math.h>

#define Bz    128
#define Sl    200
#define Dm    128
#define Hh    8
#define HD    16
#define Ll    2
#define DFF   2048
#define HID   512
#define TBLV  1000
#define IDXV  100000
#define TOUTN 8
#define NTOK  (Bz*Sl)   // 25600

// ---------------- scratch (device globals; no allocation allowed) ----------
__device__ float g_x  [NTOK*Dm];
__device__ float g_qkv[NTOK*3*Dm];
__device__ float g_att[NTOK*Dm];
__device__ float g_tmp[NTOK*Dm];
__device__ float g_ff [NTOK*DFF];
__device__ float g_hcat[Bz*2*Dm];
__device__ float g_h  [Bz*HID];

// ---------------- embedding lookup ----------------
__global__ void embed_k(const int* __restrict__ ids, const float* __restrict__ tab,
                        float* __restrict__ out)
{
    int n = blockIdx.x;
    int d = threadIdx.x;
    out[n*Dm + d] = tab[(size_t)ids[n]*Dm + d];
}

// ---------------- generic GEMM: C[M,N] = A[M,K] @ B[N,K]^T + bias ----------
// TM=TN=128, TK=16, 256 threads, 8x8 microtile.
// n-fragment interleaved (n = j*16 + tx) so every global store is coalesced.
// TOUT==8: fused time-broadcast epilogue, wlast = B[n*ldb + K].
template<int TOUT, bool RELU>
__global__ __launch_bounds__(256)
void gemm_k(const float* __restrict__ A, int lda,
            const float* __restrict__ Bm, int ldb,
            const float* __restrict__ bias,
            float* __restrict__ C, int ldc,
            int M, int N, int K)
{
    const int TM = 128, TN = 128, TK = 16;
    __shared__ float As[TK][TM + 4];   // k-major; stride 132 keeps float4 align
    __shared__ float Bs[TK][TN + 4];

    int tid = threadIdx.x;
    int tx = tid & 15;        // 0..15 -> n lanes / k-load lane
    int ty = tid >> 4;        // 0..15 -> m lanes / row-load group

    int m0 = blockIdx.y * TM;
    int n0 = blockIdx.x * TN;

    float acc[8][8];
#pragma unroll
    for (int i = 0; i < 8; i++)
#pragma unroll
        for (int j = 0; j < 8; j++) acc[i][j] = 0.f;

    for (int k0 = 0; k0 < K; k0 += TK) {
        // load A tile (M assumed multiple of 128)
#pragma unroll
        for (int i = 0; i < 8; i++) {
            int r = i*16 + ty;
            As[tx][r] = A[(size_t)(m0 + r)*lda + k0 + tx];
        }
        // load B tile (guard N edge)
#pragma unroll
        for (int i = 0; i < 8; i++) {
            int r = i*16 + ty;
            int n = n0 + r;
            Bs[tx][r] = (n < N) ? Bm[(size_t)n*ldb + k0 + tx] : 0.f;
        }
        __syncthreads();

#pragma unroll
        for (int kk = 0; kk < TK; kk++) {
            float a[8], b[8];
            float4 a0 = *(const float4*)&As[kk][ty*8];
            float4 a1 = *(const float4*)&As[kk][ty*8 + 4];
            a[0]=a0.x; a[1]=a0.y; a[2]=a0.z; a[3]=a0.w;
            a[4]=a1.x; a[5]=a1.y; a[6]=a1.z; a[7]=a1.w;
#pragma unroll
            for (int j = 0; j < 8; j++) b[j] = Bs[kk][j*16 + tx];
#pragma unroll
            for (int i = 0; i < 8; i++)
#pragma unroll
                for (int j = 0; j < 8; j++)
                    acc[i][j] = fmaf(a[i], b[j], acc[i][j]);
        }
        __syncthreads();
    }

    if (TOUT == 1) {
#pragma unroll
        for (int i = 0; i < 8; i++) {
            int m = m0 + ty*8 + i;
#pragma unroll
            for (int j = 0; j < 8; j++) {
                int n = n0 + j*16 + tx;
                if (n < N) {
                    float v = acc[i][j] + bias[n];
                    if (RELU) v = fmaxf(v, 0.f);
                    C[(size_t)m*ldc + n] = v;
                }
            }
        }
    } else {
        // time-broadcast epilogue: out[(m*TOUT+t)*ldc + n] = base + t*wlast
#pragma unroll
        for (int i = 0; i < 8; i++) {
            int m = m0 + ty*8 + i;
#pragma unroll
            for (int j = 0; j < 8; j++) {
                int n = n0 + j*16 + tx;
                if (n < N) {
                    float base = acc[i][j] + bias[n];
                    float w = Bm[(size_t)n*ldb + K];
#pragma unroll
                    for (int t = 0; t < TOUT; t++)
                        C[(size_t)(m*TOUT + t)*ldc + n] = base + (float)t * w;
                }
            }
        }
    }
}

// ---------------- per-(b,h) attention, online softmax -------------------
__global__ __launch_bounds__(256)
void attn_k(const float* __restrict__ qkv, float* __restrict__ out)
{
    int bh = blockIdx.x;
    int b = bh / Hh, h = bh % Hh;
    __shared__ float ks[Sl][HD];
    __shared__ float vs[Sl][HD];
    int tid = threadIdx.x;
    const float* base = qkv + (size_t)b*Sl*(3*Dm);

    for (int e = tid; e < Sl*HD; e += 256) {
        int s = e / HD, d = e % HD;
        ks[s][d] = base[s*(3*Dm) + Dm     + h*HD + d];
        vs[s][d] = base[s*(3*Dm) + 2*Dm   + h*HD + d];
    }
    __syncthreads();

    if (tid < Sl) {
        int s = tid;
        float q[HD];
#pragma unroll
        for (int d = 0; d < HD; d++)
            q[d] = base[s*(3*Dm) + h*HD + d] * 0.25f;   // 1/sqrt(16)

        float m = -1e30f, l = 0.f;
        float acc[HD];
#pragma unroll
        for (int d = 0; d < HD; d++) acc[d] = 0.f;

        for (int j = 0; j < Sl; j++) {
            float sc = 0.f;
#pragma unroll
            for (int d = 0; d < HD; d++) sc = fmaf(q[d], ks[j][d], sc);
            float nm  = fmaxf(m, sc);
            float cor = __expf(m - nm);
            float p   = __expf(sc - nm);
            l = l*cor + p;
#pragma unroll
            for (int d = 0; d < HD; d++) acc[d] = acc[d]*cor + p*vs[j][d];
            m = nm;
        }
        float inv = 1.f / l;
#pragma unroll
        for (int d = 0; d < HD; d++)
            out[(size_t)(b*Sl + s)*Dm + h*HD + d] = acc[d]*inv;
    }
}

// ---------------- fused residual-add + LayerNorm (in-place on x) --------
__global__ void add_ln_k(float* __restrict__ x, const float* __restrict__ r,
                         const float* __restrict__ g, const float* __restrict__ b)
{
    int n = blockIdx.x, d = threadIdx.x;
    __shared__ float red[8];
    float v = x[(size_t)n*Dm + d] + r[(size_t)n*Dm + d];

    float s = v;
#pragma unroll
    for (int o = 16; o > 0; o >>= 1) s += __shfl_xor_sync(0xffffffffu, s, o);
    if ((d & 31) == 0) red[d >> 5] = s;
    __syncthreads();
    float mean = (red[0]+red[1]+red[2]+red[3]) * (1.f/Dm);

    float c = v - mean;
    float s2 = c*c;
#pragma unroll
    for (int o = 16; o > 0; o >>= 1) s2 += __shfl_xor_sync(0xffffffffu, s2, o);
    if ((d & 31) == 0) red[4 + (d >> 5)] = s2;
    __syncthreads();
    float var = (red[4]+red[5]+red[6]+red[7]) * (1.f/Dm);

    x[(size_t)n*Dm + d] = c * rsqrtf(var + 1e-5f) * g[d] + b[d];
}

// ---------------- sequence mean into hcat -------------------------------
__global__ void mean_k(const float* __restrict__ x, float* __restrict__ out, int off)
{
    int b = blockIdx.x, d = threadIdx.x;
    float s = 0.f;
    for (int j = 0; j < Sl; j++) s += x[(size_t)(b*Sl + j)*Dm + d];
    out[b*(2*Dm) + off + d] = s * (1.f/Sl);
}

// ---------------- launcher ----------------------------------------------
extern "C" void kernel_launch(void* const* d_in, const int* in_sizes, int n_in,
                              void* d_out, int out_size)
{
    const int*   tid_seq = (const int*)  d_in[0];
    const int*   iid_seq = (const int*)  d_in[1];
    const float* tab_emb = (const float*)d_in[2];
    const float* idx_emb = (const float*)d_in[3];
    const float* Wqkv = (const float*)d_in[4];
    const float* bqkv = (const float*)d_in[5];
    const float* Wo   = (const float*)d_in[6];
    const float* bo   = (const float*)d_in[7];
    const float* ln1g = (const float*)d_in[8];
    const float* ln1b = (const float*)d_in[9];
    const float* W1   = (const float*)d_in[10];
    const float* b1   = (const float*)d_in[11];
    const float* W2   = (const float*)d_in[12];
    const float* b2   = (const float*)d_in[13];
    const float* ln2g = (const float*)d_in[14];
    const float* ln2b = (const float*)d_in[15];
    const float* Wlin = (const float*)d_in[16];
    const float* blin = (const float*)d_in[17];
    const float* Wtab = (const float*)d_in[18];
    const float* btab = (const float*)d_in[19];
    const float* Widx = (const float*)d_in[20];
    const float* bidx = (const float*)d_in[21];

    float* out     = (float*)d_out;
    float* out_tab = out;
    float* out_idx = out + (size_t)Bz*TOUTN*TBLV;

    float *x, *qkv, *att, *tmp, *ff, *hcat, *h;
    cudaGetSymbolAddress((void**)&x,    g_x);
    cudaGetSymbolAddress((void**)&qkv,  g_qkv);
    cudaGetSymbolAddress((void**)&att,  g_att);
    cudaGetSymbolAddress((void**)&tmp,  g_tmp);
    cudaGetSymbolAddress((void**)&ff,   g_ff);
    cudaGetSymbolAddress((void**)&hcat, g_hcat);
    cudaGetSymbolAddress((void**)&h,    g_h);

    const int MT = NTOK / 128;  // 200 row-tiles

    for (int e = 0; e < 2; e++) {
        embed_k<<<NTOK, Dm>>>(e == 0 ? tid_seq : iid_seq,
                              e == 0 ? tab_emb : idx_emb, x);
        for (int l = 0; l < Ll; l++) {
            int wi = e*Ll + l;
            // qkv = x @ Wqkv^T + b
            gemm_k<1,false><<<dim3(3, MT), 256>>>(
                x, Dm, Wqkv + (size_t)wi*3*Dm*Dm, Dm, bqkv + wi*3*Dm,
                qkv, 3*Dm, NTOK, 3*Dm, Dm);
            // attention
            attn_k<<<Bz*Hh, 256>>>(qkv, att);
            // o proj
            gemm_k<1,false><<<dim3(1, MT), 256>>>(
                att, Dm, Wo + (size_t)wi*Dm*Dm, Dm, bo + wi*Dm,
                tmp, Dm, NTOK, Dm, Dm);
            // x = LN(x + o)
            add_ln_k<<<NTOK, Dm>>>(x, tmp, ln1g + wi*Dm, ln1b + wi*Dm);
            // ff = relu(x @ W1^T + b1)
            gemm_k<1,true><<<dim3(DFF/128, MT), 256>>>(
                x, Dm, W1 + (size_t)wi*DFF*Dm, Dm, b1 + wi*DFF,
                ff, DFF, NTOK, DFF, Dm);
            // tmp = ff @ W2^T + b2
            gemm_k<1,false><<<dim3(1, MT), 256>>>(
                ff, DFF, W2 + (size_t)wi*Dm*DFF, DFF, b2 + wi*Dm,
                tmp, Dm, NTOK, Dm, DFF);
            // x = LN(x + ff_out)
            add_ln_k<<<NTOK, Dm>>>(x, tmp, ln2g + wi*Dm, ln2b + wi*Dm);
        }
        mean_k<<<Bz, Dm>>>(x, hcat, e*Dm);
    }

    // h = relu(hcat @ Wlin^T + blin)    [128,256]@[256,512]
    gemm_k<1,true><<<dim3(HID/128, 1), 256>>>(
        hcat, 2*Dm, Wlin, 2*Dm, blin, h, HID, Bz, HID, 2*Dm);

    // tab: [128,1000] base + t-broadcast -> [1024,1000]
    gemm_k<TOUTN,false><<<dim3((TBLV + 127)/128, 1), 256>>>(
        h, HID, Wtab, HID + 1, btab, out_tab, TBLV, Bz, TBLV, HID);

    // idx: [128,100000] base + t-broadcast -> [1024,100000]
    gemm_k<TOUTN,false><<<dim3((IDXV + 127)/128, 1), 256>>>(
        h, HID, Widx, HID + 1, bidx, out_idx, IDXV, Bz, IDXV, HID);
}

// round 2
// speedup vs baseline: 1.0478x; 1.0478x over previous
#include <cuda_runtime.h>
#include <math.h>

#define Bz    128
#define Sl    200
#define Dm    128
#define Hh    8
#define HD    16
#define Ll    2
#define DFF   2048
#define HID   512
#define TBLV  1000
#define IDXV  100000
#define TOUTN 8
#define NTOK  (Bz*Sl)   // 25600

// ---------------- scratch (device globals; no allocation allowed) ----------
__device__ float g_x  [2*NTOK*Dm];
__device__ float g_qkv[2*NTOK*3*Dm];
__device__ float g_att[2*NTOK*Dm];
__device__ float g_tmp[2*NTOK*Dm];
__device__ float g_ff [(size_t)2*NTOK*DFF];
__device__ float g_hcat[Bz*2*Dm];
__device__ float g_h  [Bz*HID];

// ---------------- embedding lookup (both encoders, z = blockIdx.y) ---------
__global__ void embed2_k(const int* __restrict__ ids0, const int* __restrict__ ids1,
                         const float* __restrict__ t0, const float* __restrict__ t1,
                         float* __restrict__ out)
{
    int z = blockIdx.y;
    int n = blockIdx.x;
    int d = threadIdx.x;
    const int*   ids = z ? ids1 : ids0;
    const float* tab = z ? t1   : t0;
    out[((size_t)z*NTOK + n)*Dm + d] = tab[(size_t)ids[n]*Dm + d];
}

// ---------------- GEMM: C[M,N] = A[M,K] @ B[N,K]^T + bias ------------------
// TM=TN=128, TK=16, 256 threads, 8x8 microtile. Double-buffered smem with
// register prefetch. blockIdx.z selects encoder (strides sA/sB/sBias/sC).
// VECB: float4 B-tile loads (requires ldb%4==0 and 16B-aligned rows).
// TOUT==8: fused time-broadcast epilogue, wlast = B[n*ldb + K].
template<int TOUT, bool RELU, bool VECB>
__global__ __launch_bounds__(256)
void gemm_k(const float* __restrict__ A, int lda, size_t sA,
            const float* __restrict__ Bm, int ldb, size_t sB,
            const float* __restrict__ bias, size_t sBias,
            float* __restrict__ C, int ldc, size_t sC,
            int M, int N, int K)
{
    const int TM = 128, TN = 128, TK = 16;
    __shared__ float As[2][TK][TM + 4];
    __shared__ float Bs[2][TK][TN + 4];

    int z = blockIdx.z;
    A    += (size_t)z * sA;
    Bm   += (size_t)z * sB;
    bias += (size_t)z * sBias;
    C    += (size_t)z * sC;

    int t  = threadIdx.x;
    int tx = t & 15;          // 0..15 : n lane
    int ty = t >> 4;          // 0..15 : m lane

    int m0 = blockIdx.y * TM;
    int n0 = blockIdx.x * TN;

    // ---- tile loaders -------------------------------------------------
    int lr  = t >> 2;         // 0..63
    int lc4 = (t & 3) * 4;    // k offset within tile (float4 granularity)
    const float* Arow0 = A + (size_t)(m0 + lr)      * lda + lc4;
    const float* Arow1 = A + (size_t)(m0 + lr + 64) * lda + lc4;

    float4 pa0, pa1;
    float4 pb0v, pb1v;        // vector-B path
    float  pbs[8];            // scalar-B path

    const float* Brow0 = nullptr; const float* Brow1 = nullptr;
    bool bv0 = false, bv1 = false;
    if (VECB) {
        bv0 = (n0 + lr)      < N;
        bv1 = (n0 + lr + 64) < N;
        Brow0 = Bm + (size_t)(n0 + lr)      * ldb + lc4;
        Brow1 = Bm + (size_t)(n0 + lr + 64) * ldb + lc4;
    }

    float acc[8][8];
#pragma unroll
    for (int i = 0; i < 8; i++)
#pragma unroll
        for (int j = 0; j < 8; j++) acc[i][j] = 0.f;

    const int nk = K / TK;

    // prologue: load tile 0
    pa0 = *(const float4*)(Arow0);
    pa1 = *(const float4*)(Arow1);
    if (VECB) {
        pb0v = bv0 ? *(const float4*)(Brow0) : make_float4(0,0,0,0);
        pb1v = bv1 ? *(const float4*)(Brow1) : make_float4(0,0,0,0);
    } else {
#pragma unroll
        for (int i = 0; i < 8; i++) {
            int n = n0 + i*16 + ty;
            pbs[i] = (n < N) ? Bm[(size_t)n*ldb + tx] : 0.f;
        }
    }
    // store tile 0
    {
        As[0][lc4+0][lr] = pa0.x; As[0][lc4+1][lr] = pa0.y;
        As[0][lc4+2][lr] = pa0.z; As[0][lc4+3][lr] = pa0.w;
        As[0][lc4+0][lr+64] = pa1.x; As[0][lc4+1][lr+64] = pa1.y;
        As[0][lc4+2][lr+64] = pa1.z; As[0][lc4+3][lr+64] = pa1.w;
        if (VECB) {
            Bs[0][lc4+0][lr] = pb0v.x; Bs[0][lc4+1][lr] = pb0v.y;
            Bs[0][lc4+2][lr] = pb0v.z; Bs[0][lc4+3][lr] = pb0v.w;
            Bs[0][lc4+0][lr+64] = pb1v.x; Bs[0][lc4+1][lr+64] = pb1v.y;
            Bs[0][lc4+2][lr+64] = pb1v.z; Bs[0][lc4+3][lr+64] = pb1v.w;
        } else {
#pragma unroll
            for (int i = 0; i < 8; i++) Bs[0][tx][i*16 + ty] = pbs[i];
        }
    }
    __syncthreads();

    for (int it = 0; it < nk; ++it) {
        int buf = it & 1;
        bool more = (it + 1) < nk;
        int knext = (it + 1) * TK;

        if (more) {
            pa0 = *(const float4*)(Arow0 + knext);
            pa1 = *(const float4*)(Arow1 + knext);
            if (VECB) {
                pb0v = bv0 ? *(const float4*)(Brow0 + knext) : make_float4(0,0,0,0);
                pb1v = bv1 ? *(const float4*)(Brow1 + knext) : make_float4(0,0,0,0);
            } else {
#pragma unroll
                for (int i = 0; i < 8; i++) {
                    int n = n0 + i*16 + ty;
                    pbs[i] = (n < N) ? Bm[(size_t)n*ldb + knext + tx] : 0.f;
                }
            }
        }

#pragma unroll
        for (int kk = 0; kk < TK; kk++) {
            float a[8], b[8];
            float4 a0 = *(const float4*)&As[buf][kk][ty*8];
            float4 a1 = *(const float4*)&As[buf][kk][ty*8 + 4];
            a[0]=a0.x; a[1]=a0.y; a[2]=a0.z; a[3]=a0.w;
            a[4]=a1.x; a[5]=a1.y; a[6]=a1.z; a[7]=a1.w;
#pragma unroll
            for (int j = 0; j < 8; j++) b[j] = Bs[buf][kk][j*16 + tx];
#pragma unroll
            for (int i = 0; i < 8; i++)
#pragma unroll
                for (int j = 0; j < 8; j++)
                    acc[i][j] = fmaf(a[i], b[j], acc[i][j]);
        }

        if (more) {
            int nb = buf ^ 1;
            As[nb][lc4+0][lr] = pa0.x; As[nb][lc4+1][lr] = pa0.y;
            As[nb][lc4+2][lr] = pa0.z; As[nb][lc4+3][lr] = pa0.w;
            As[nb][lc4+0][lr+64] = pa1.x; As[nb][lc4+1][lr+64] = pa1.y;
            As[nb][lc4+2][lr+64] = pa1.z; As[nb][lc4+3][lr+64] = pa1.w;
            if (VECB) {
                Bs[nb][lc4+0][lr] = pb0v.x; Bs[nb][lc4+1][lr] = pb0v.y;
                Bs[nb][lc4+2][lr] = pb0v.z; Bs[nb][lc4+3][lr] = pb0v.w;
                Bs[nb][lc4+0][lr+64] = pb1v.x; Bs[nb][lc4+1][lr+64] = pb1v.y;
                Bs[nb][lc4+2][lr+64] = pb1v.z; Bs[nb][lc4+3][lr+64] = pb1v.w;
            } else {
#pragma unroll
                for (int i = 0; i < 8; i++) Bs[nb][tx][i*16 + ty] = pbs[i];
            }
            __syncthreads();
        }
    }

    if (TOUT == 1) {
#pragma unroll
        for (int i = 0; i < 8; i++) {
            int m = m0 + ty*8 + i;
#pragma unroll
            for (int j = 0; j < 8; j++) {
                int n = n0 + j*16 + tx;
                if (n < N) {
                    float v = acc[i][j] + bias[n];
                    if (RELU) v = fmaxf(v, 0.f);
                    C[(size_t)m*ldc + n] = v;
                }
            }
        }
    } else {
        // time-broadcast epilogue: out[(m*TOUT+t)*ldc + n] = base + t*wlast
#pragma unroll
        for (int i = 0; i < 8; i++) {
            int m = m0 + ty*8 + i;
#pragma unroll
            for (int j = 0; j < 8; j++) {
                int n = n0 + j*16 + tx;
                if (n < N) {
                    float base = acc[i][j] + bias[n];
                    float w = Bm[(size_t)n*ldb + K];
#pragma unroll
                    for (int tt = 0; tt < TOUT; tt++)
                        C[(size_t)(m*TOUT + tt)*ldc + n] = base + (float)tt * w;
                }
            }
        }
    }
}

// ---------------- per-(b,h) attention, online softmax -------------------
__global__ __launch_bounds__(256)
void attn_k(const float* __restrict__ qkv, float* __restrict__ out)
{
    int z = blockIdx.y;
    int bh = blockIdx.x;
    int b = bh / Hh, h = bh % Hh;
    __shared__ float ks[Sl][HD];
    __shared__ float vs[Sl][HD];
    int tid = threadIdx.x;
    const float* base = qkv + ((size_t)z*NTOK + (size_t)b*Sl)*(3*Dm);

    for (int e = tid; e < Sl*HD; e += 256) {
        int s = e / HD, d = e % HD;
        ks[s][d] = base[s*(3*Dm) + Dm   + h*HD + d];
        vs[s][d] = base[s*(3*Dm) + 2*Dm + h*HD + d];
    }
    __syncthreads();

    if (tid < Sl) {
        int s = tid;
        float q[HD];
#pragma unroll
        for (int d = 0; d < HD; d++)
            q[d] = base[s*(3*Dm) + h*HD + d] * 0.25f;   // 1/sqrt(16)

        float m = -1e30f, l = 0.f;
        float acc[HD];
#pragma unroll
        for (int d = 0; d < HD; d++) acc[d] = 0.f;

        for (int j = 0; j < Sl; j++) {
            float sc = 0.f;
#pragma unroll
            for (int d = 0; d < HD; d++) sc = fmaf(q[d], ks[j][d], sc);
            float nm  = fmaxf(m, sc);
            float cor = __expf(m - nm);
            float p   = __expf(sc - nm);
            l = l*cor + p;
#pragma unroll
            for (int d = 0; d < HD; d++) acc[d] = acc[d]*cor + p*vs[j][d];
            m = nm;
        }
        float inv = 1.f / l;
#pragma unroll
        for (int d = 0; d < HD; d++)
            out[((size_t)z*NTOK + (size_t)b*Sl + s)*Dm + h*HD + d] = acc[d]*inv;
    }
}

// ---------------- fused residual-add + LayerNorm (in-place on x) --------
__global__ void add_ln_k(float* __restrict__ x, const float* __restrict__ r,
                         const float* __restrict__ g, const float* __restrict__ b,
                         size_t sW)
{
    int z = blockIdx.y;
    int n = blockIdx.x, d = threadIdx.x;
    size_t tok = (size_t)z*NTOK + n;
    g += (size_t)z * sW;
    b += (size_t)z * sW;
    __shared__ float red[8];
    float v = x[tok*Dm + d] + r[tok*Dm + d];

    float s = v;
#pragma unroll
    for (int o = 16; o > 0; o >>= 1) s += __shfl_xor_sync(0xffffffffu, s, o);
    if ((d & 31) == 0) red[d >> 5] = s;
    __syncthreads();
    float mean = (red[0]+red[1]+red[2]+red[3]) * (1.f/Dm);

    float c = v - mean;
    float s2 = c*c;
#pragma unroll
    for (int o = 16; o > 0; o >>= 1) s2 += __shfl_xor_sync(0xffffffffu, s2, o);
    if ((d & 31) == 0) red[4 + (d >> 5)] = s2;
    __syncthreads();
    float var = (red[4]+red[5]+red[6]+red[7]) * (1.f/Dm);

    x[tok*Dm + d] = c * rsqrtf(var + 1e-5f) * g[d] + b[d];
}

// ---------------- sequence mean into hcat -------------------------------
__global__ void mean_k(const float* __restrict__ x, float* __restrict__ out)
{
    int z = blockIdx.y;
    int b = blockIdx.x, d = threadIdx.x;
    const float* xp = x + ((size_t)z*NTOK + (size_t)b*Sl)*Dm;
    float s = 0.f;
    for (int j = 0; j < Sl; j++) s += xp[j*Dm + d];
    out[b*(2*Dm) + z*Dm + d] = s * (1.f/Sl);
}

// ---------------- launcher ----------------------------------------------
extern "C" void kernel_launch(void* const* d_in, const int* in_sizes, int n_in,
                              void* d_out, int out_size)
{
    const int*   tid_seq = (const int*)  d_in[0];
    const int*   iid_seq = (const int*)  d_in[1];
    const float* tab_emb = (const float*)d_in[2];
    const float* idx_emb = (const float*)d_in[3];
    const float* Wqkv = (const float*)d_in[4];
    const float* bqkv = (const float*)d_in[5];
    const float* Wo   = (const float*)d_in[6];
    const float* bo   = (const float*)d_in[7];
    const float* ln1g = (const float*)d_in[8];
    const float* ln1b = (const float*)d_in[9];
    const float* W1   = (const float*)d_in[10];
    const float* b1   = (const float*)d_in[11];
    const float* W2   = (const float*)d_in[12];
    const float* b2   = (const float*)d_in[13];
    const float* ln2g = (const float*)d_in[14];
    const float* ln2b = (const float*)d_in[15];
    const float* Wlin = (const float*)d_in[16];
    const float* blin = (const float*)d_in[17];
    const float* Wtab = (const float*)d_in[18];
    const float* btab = (const float*)d_in[19];
    const float* Widx = (const float*)d_in[20];
    const float* bidx = (const float*)d_in[21];

    float* out     = (float*)d_out;
    float* out_tab = out;
    float* out_idx = out + (size_t)Bz*TOUTN*TBLV;

    float *x, *qkv, *att, *tmp, *ff, *hcat, *h;
    cudaGetSymbolAddress((void**)&x,    g_x);
    cudaGetSymbolAddress((void**)&qkv,  g_qkv);
    cudaGetSymbolAddress((void**)&att,  g_att);
    cudaGetSymbolAddress((void**)&tmp,  g_tmp);
    cudaGetSymbolAddress((void**)&ff,   g_ff);
    cudaGetSymbolAddress((void**)&hcat, g_hcat);
    cudaGetSymbolAddress((void**)&h,    g_h);

    const int MT = NTOK / 128;  // 200 row-tiles
    const size_t sX   = (size_t)NTOK*Dm;
    const size_t sQKV = (size_t)NTOK*3*Dm;
    const size_t sFF  = (size_t)NTOK*DFF;

    embed2_k<<<dim3(NTOK, 2), Dm>>>(tid_seq, iid_seq, tab_emb, idx_emb, x);

    for (int l = 0; l < Ll; l++) {
        // qkv = x @ Wqkv^T + b           (both encoders via z)
        gemm_k<1,false,true><<<dim3(3, MT, 2), 256>>>(
            x, Dm, sX,
            Wqkv + (size_t)l*3*Dm*Dm, Dm, (size_t)Ll*3*Dm*Dm,
            bqkv + (size_t)l*3*Dm, (size_t)Ll*3*Dm,
            qkv, 3*Dm, sQKV, NTOK, 3*Dm, Dm);

        attn_k<<<dim3(Bz*Hh, 2), 256>>>(qkv, att);

        // o proj
        gemm_k<1,false,true><<<dim3(1, MT, 2), 256>>>(
            att, Dm, sX,
            Wo + (size_t)l*Dm*Dm, Dm, (size_t)Ll*Dm*Dm,
            bo + (size_t)l*Dm, (size_t)Ll*Dm,
            tmp, Dm, sX, NTOK, Dm, Dm);

        add_ln_k<<<dim3(NTOK, 2), Dm>>>(x, tmp, ln1g + (size_t)l*Dm, ln1b + (size_t)l*Dm,
                                        (size_t)Ll*Dm);

        // ff = relu(x @ W1^T + b1)
        gemm_k<1,true,true><<<dim3(DFF/128, MT, 2), 256>>>(
            x, Dm, sX,
            W1 + (size_t)l*DFF*Dm, Dm, (size_t)Ll*DFF*Dm,
            b1 + (size_t)l*DFF, (size_t)Ll*DFF,
            ff, DFF, sFF, NTOK, DFF, Dm);

        // tmp = ff @ W2^T + b2
        gemm_k<1,false,true><<<dim3(1, MT, 2), 256>>>(
            ff, DFF, sFF,
            W2 + (size_t)l*Dm*DFF, DFF, (size_t)Ll*Dm*DFF,
            b2 + (size_t)l*Dm, (size_t)Ll*Dm,
            tmp, Dm, sX, NTOK, Dm, DFF);

        add_ln_k<<<dim3(NTOK, 2), Dm>>>(x, tmp, ln2g + (size_t)l*Dm, ln2b + (size_t)l*Dm,
                                        (size_t)Ll*Dm);
    }

    mean_k<<<dim3(Bz, 2), Dm>>>(x, hcat);

    // h = relu(hcat @ Wlin^T + blin)    [128,256]@[256,512]
    gemm_k<1,true,true><<<dim3(HID/128, 1, 1), 256>>>(
        hcat, 2*Dm, 0, Wlin, 2*Dm, 0, blin, 0,
        h, HID, 0, Bz, HID, 2*Dm);

    // tab: [128,1000] base + t-broadcast -> [1024,1000]   (ldb=513 -> scalar B)
    gemm_k<TOUTN,false,false><<<dim3((TBLV + 127)/128, 1, 1), 256>>>(
        h, HID, 0, Wtab, HID + 1, 0, btab, 0,
        out_tab, TBLV, 0, Bz, TBLV, HID);

    // idx: [128,100000] base + t-broadcast -> [1024,100000]
    gemm_k<TOUTN,false,false><<<dim3((IDXV + 127)/128, 1, 1), 256>>>(
        h, HID, 0, Widx, HID + 1, 0, bidx, 0,
        out_idx, IDXV, 0, Bz, IDXV, HID);
}

// round 4
// speedup vs baseline: 1.2945x; 1.2355x over previous
#include <cuda_runtime.h>
#include <cuda_bf16.h>
#include <math.h>
#include <stdint.h>

#define Bz    128
#define Sl    200
#define Dm    128
#define Hh    8
#define HD    16
#define Ll    2
#define DFF   2048
#define HID   512
#define TBLV  1000
#define IDXV  100000
#define TOUTN 8
#define NTOK  (Bz*Sl)   // 25600

// ================= scratch (device globals) =================
__device__ float g_x   [2*NTOK*Dm];
__device__ float g_qkv [2*NTOK*3*Dm];
__device__ float g_tmp [2*NTOK*Dm];
__device__ float g_hcat[Bz*2*Dm];
__device__ float g_h   [Bz*HID];
__device__ __nv_bfloat16 g_xh [2*NTOK*Dm];
__device__ __nv_bfloat16 g_xl [2*NTOK*Dm];
__device__ __nv_bfloat16 g_ath[2*NTOK*Dm];
__device__ __nv_bfloat16 g_atl[2*NTOK*Dm];
__device__ __nv_bfloat16 g_ffh[(size_t)2*NTOK*DFF];
__device__ __nv_bfloat16 g_ffl[(size_t)2*NTOK*DFF];
__device__ __nv_bfloat16 g_Wqkvh[2*Ll*3*Dm*Dm], g_Wqkvl[2*Ll*3*Dm*Dm];
__device__ __nv_bfloat16 g_Woh  [2*Ll*Dm*Dm],   g_Wol  [2*Ll*Dm*Dm];
__device__ __nv_bfloat16 g_W1h  [2*Ll*DFF*Dm],  g_W1l  [2*Ll*DFF*Dm];
__device__ __nv_bfloat16 g_W2h  [2*Ll*Dm*DFF],  g_W2l  [2*Ll*Dm*DFF];

// ================= mma helpers (baseline PTX, no sm_103a features) ==========
__device__ __forceinline__ uint32_t smem_u32(const void* p) {
    uint32_t a;
    asm("{ .reg .u64 t; cvta.to.shared.u64 t, %1; cvt.u32.u64 %0, t; }"
        : "=r"(a) : "l"(p));
    return a;
}
__device__ __forceinline__ void ldm_x4(uint32_t* r, uint32_t addr) {
    asm volatile("ldmatrix.sync.aligned.m8n8.x4.shared.b16 {%0,%1,%2,%3}, [%4];"
        : "=r"(r[0]), "=r"(r[1]), "=r"(r[2]), "=r"(r[3]) : "r"(addr));
}
__device__ __forceinline__ void mma16816(float* c, const uint32_t* a,
                                         uint32_t b0, uint32_t b1) {
    asm volatile("mma.sync.aligned.m16n8k16.row.col.f32.bf16.bf16.f32 "
        "{%0,%1,%2,%3}, {%4,%5,%6,%7}, {%8,%9}, {%0,%1,%2,%3};"
        : "+f"(c[0]), "+f"(c[1]), "+f"(c[2]), "+f"(c[3])
        : "r"(a[0]), "r"(a[1]), "r"(a[2]), "r"(a[3]), "r"(b0), "r"(b1));
}

// ================= small utility kernels =================
__global__ void cvt_k(const float* __restrict__ in, __nv_bfloat16* __restrict__ h,
                      __nv_bfloat16* __restrict__ l, int n)
{
    int i = blockIdx.x * 256 + threadIdx.x;
    if (i < n) {
        float v = in[i];
        __nv_bfloat16 hi = __float2bfloat16(v);
        h[i] = hi;
        l[i] = __float2bfloat16(v - __bfloat162float(hi));
    }
}

__global__ void embed2_k(const int* __restrict__ ids0, const int* __restrict__ ids1,
                         const float* __restrict__ t0, const float* __restrict__ t1,
                         float* __restrict__ out,
                         __nv_bfloat16* __restrict__ oh, __nv_bfloat16* __restrict__ ol)
{
    int z = blockIdx.y, n = blockIdx.x, d = threadIdx.x;
    const int*   ids = z ? ids1 : ids0;
    const float* tab = z ? t1   : t0;
    size_t o = ((size_t)z*NTOK + n)*Dm + d;
    float v = tab[(size_t)ids[n]*Dm + d];
    out[o] = v;
    __nv_bfloat16 hi = __float2bfloat16(v);
    oh[o] = hi;
    ol[o] = __float2bfloat16(v - __bfloat162float(hi));
}

// ================= split-bf16 tensor-core GEMM ==============================
// C[M,N] = (Ah+Al)[M,K] @ (Bh+Bl)[N,K]^T + bias   (AlBl dropped, ~2^-18 rel)
// Block tile 128x128, BK=16, 8 warps (4x2), warp tile 32x64.
// smem: 4 tiles x 128 rows x 48B pitch (32B data + 16B pad -> ldmatrix
// conflict-free), double-buffered = 48KB.
#define PITCH 48
#define TILEB (128*PITCH)

template<bool RELU, bool OUTBF16>
__global__ __launch_bounds__(256)
void gemm_mma(const __nv_bfloat16* __restrict__ Ah, const __nv_bfloat16* __restrict__ Al,
              int lda, size_t sA,
              const __nv_bfloat16* __restrict__ Bh, const __nv_bfloat16* __restrict__ Bl,
              int ldb, size_t sB,
              const float* __restrict__ bias, size_t sBias,
              float* __restrict__ Cf,
              __nv_bfloat16* __restrict__ Ch, __nv_bfloat16* __restrict__ Cl,
              int ldc, size_t sC, int K)
{
    __shared__ __align__(16) char sm[2][4][TILEB];   // [buf][Ah,Al,Bh,Bl]

    int tid  = threadIdx.x;
    int wid  = tid >> 5;
    int lane = tid & 31;
    int z = blockIdx.z;
    Ah += (size_t)z * sA;  Al += (size_t)z * sA;
    Bh += (size_t)z * sB;  Bl += (size_t)z * sB;
    bias += (size_t)z * sBias;
    if (OUTBF16) { Ch += (size_t)z * sC; Cl += (size_t)z * sC; }
    else         { Cf += (size_t)z * sC; }

    int m0 = blockIdx.y * 128;
    int n0 = blockIdx.x * 128;

    // ---- loader mapping: thread -> (row 0..127, half 0..1) of each tile ----
    int lrow = tid >> 1, lhalf = tid & 1;
    const __nv_bfloat16* pAh = Ah + (size_t)(m0 + lrow)*lda + lhalf*8;
    const __nv_bfloat16* pAl = Al + (size_t)(m0 + lrow)*lda + lhalf*8;
    const __nv_bfloat16* pBh = Bh + (size_t)(n0 + lrow)*ldb + lhalf*8;
    const __nv_bfloat16* pBl = Bl + (size_t)(n0 + lrow)*ldb + lhalf*8;
    int sdst = lrow*PITCH + lhalf*16;

    // ---- compute mapping ----
    int wm = wid & 3;        // 4 m-groups of 32 rows
    int wn = wid >> 2;       // 2 n-groups of 64 cols
    int r8 = lane & 7, quad = lane >> 3;
    int arow = wm*32 + (quad & 1)*8 + r8;      // + mi*16
    int aoff = (quad >> 1)*16;
    int brow = wn*64 + (quad >> 1)*8 + r8;     // + pj*16
    int boff = (quad & 1)*16;

    float acc[2][8][4];
#pragma unroll
    for (int i = 0; i < 2; i++)
#pragma unroll
        for (int j = 0; j < 8; j++)
#pragma unroll
            for (int c = 0; c < 4; c++) acc[i][j][c] = 0.f;

    const int nk = K / 16;
    uint4 va, vb, vc, vd;

    // prologue: tile 0
    va = *(const uint4*)(pAh); vb = *(const uint4*)(pAl);
    vc = *(const uint4*)(pBh); vd = *(const uint4*)(pBl);
    *(uint4*)(sm[0][0] + sdst) = va;  *(uint4*)(sm[0][1] + sdst) = vb;
    *(uint4*)(sm[0][2] + sdst) = vc;  *(uint4*)(sm[0][3] + sdst) = vd;

    for (int it = 0; it < nk; ++it) {
        int buf = it & 1;
        bool more = (it + 1) < nk;
        if (more) {
            int k1 = (it + 1) * 16;
            va = *(const uint4*)(pAh + k1); vb = *(const uint4*)(pAl + k1);
            vc = *(const uint4*)(pBh + k1); vd = *(const uint4*)(pBl + k1);
        }
        __syncthreads();

        uint32_t bAh = smem_u32(sm[buf][0]);
        uint32_t bAl = smem_u32(sm[buf][1]);
        uint32_t bBh = smem_u32(sm[buf][2]);
        uint32_t bBl = smem_u32(sm[buf][3]);

        uint32_t ah[2][4], al[2][4];
#pragma unroll
        for (int mi = 0; mi < 2; mi++) {
            ldm_x4(ah[mi], bAh + (arow + mi*16)*PITCH + aoff);
            ldm_x4(al[mi], bAl + (arow + mi*16)*PITCH + aoff);
        }
#pragma unroll
        for (int pj = 0; pj < 4; pj++) {
            uint32_t bh4[4], bl4[4];
            ldm_x4(bh4, bBh + (brow + pj*16)*PITCH + boff);
            ldm_x4(bl4, bBl + (brow + pj*16)*PITCH + boff);
#pragma unroll
            for (int mi = 0; mi < 2; mi++) {
                mma16816(acc[mi][2*pj],   ah[mi], bh4[0], bh4[1]);
                mma16816(acc[mi][2*pj+1], ah[mi], bh4[2], bh4[3]);
                mma16816(acc[mi][2*pj],   al[mi], bh4[0], bh4[1]);
                mma16816(acc[mi][2*pj+1], al[mi], bh4[2], bh4[3]);
                mma16816(acc[mi][2*pj],   ah[mi], bl4[0], bl4[1]);
                mma16816(acc[mi][2*pj+1], ah[mi], bl4[2], bl4[3]);
            }
        }

        if (more) {
            int nb = buf ^ 1;
            *(uint4*)(sm[nb][0] + sdst) = va;  *(uint4*)(sm[nb][1] + sdst) = vb;
            *(uint4*)(sm[nb][2] + sdst) = vc;  *(uint4*)(sm[nb][3] + sdst) = vd;
        }
    }

    // ---- epilogue ----
    int mrow0 = m0 + wm*32 + (lane >> 2);
    int ncol0 = n0 + wn*64 + (lane & 3)*2;
#pragma unroll
    for (int mi = 0; mi < 2; mi++) {
#pragma unroll
        for (int nj = 0; nj < 8; nj++) {
            int col = ncol0 + nj*8;
            float b0 = bias[col], b1 = bias[col + 1];
#pragma unroll
            for (int half = 0; half < 2; half++) {
                int row = mrow0 + mi*16 + half*8;
                float v0 = acc[mi][nj][2*half]     + b0;
                float v1 = acc[mi][nj][2*half + 1] + b1;
                if (RELU) { v0 = fmaxf(v0, 0.f); v1 = fmaxf(v1, 0.f); }
                if (OUTBF16) {
                    __nv_bfloat16 h0 = __float2bfloat16(v0);
                    __nv_bfloat16 h1 = __float2bfloat16(v1);
                    __nv_bfloat162 hp; hp.x = h0; hp.y = h1;
                    __nv_bfloat162 lp;
                    lp.x = __float2bfloat16(v0 - __bfloat162float(h0));
                    lp.y = __float2bfloat16(v1 - __bfloat162float(h1));
                    *(__nv_bfloat162*)(Ch + (size_t)row*ldc + col) = hp;
                    *(__nv_bfloat162*)(Cl + (size_t)row*ldc + col) = lp;
                } else {
                    float2 v; v.x = v0; v.y = v1;
                    *(float2*)(Cf + (size_t)row*ldc + col) = v;
                }
            }
        }
    }
}

// ================= SIMT GEMM (final projections only) =================
template<int TOUT, bool RELU>
__global__ __launch_bounds__(256)
void gemm_k(const float* __restrict__ A, int lda,
            const float* __restrict__ Bm, int ldb,
            const float* __restrict__ bias,
            float* __restrict__ C, int ldc,
            int M, int N, int K)
{
    const int TK = 16;
    __shared__ float As[TK][128 + 4];
    __shared__ float Bs[TK][128 + 4];
    int t  = threadIdx.x;
    int tx = t & 15, ty = t >> 4;
    int m0 = blockIdx.y * 128, n0 = blockIdx.x * 128;

    float acc[8][8];
#pragma unroll
    for (int i = 0; i < 8; i++)
#pragma unroll
        for (int j = 0; j < 8; j++) acc[i][j] = 0.f;

    for (int k0 = 0; k0 < K; k0 += TK) {
#pragma unroll
        for (int i = 0; i < 8; i++) {
            int r = i*16 + ty;
            int mrow = m0 + r;
            As[tx][r] = (mrow < M) ? A[(size_t)mrow*lda + k0 + tx] : 0.f;
            int n = n0 + r;
            Bs[tx][r] = (n < N) ? Bm[(size_t)n*ldb + k0 + tx] : 0.f;
        }
        __syncthreads();
#pragma unroll
        for (int kk = 0; kk < TK; kk++) {
            float a[8], b[8];
#pragma unroll
            for (int i = 0; i < 8; i++) a[i] = As[kk][ty*8 + i];
#pragma unroll
            for (int j = 0; j < 8; j++) b[j] = Bs[kk][j*16 + tx];
#pragma unroll
            for (int i = 0; i < 8; i++)
#pragma unroll
                for (int j = 0; j < 8; j++)
                    acc[i][j] = fmaf(a[i], b[j], acc[i][j]);
        }
        __syncthreads();
    }

#pragma unroll
    for (int i = 0; i < 8; i++) {
        int m = m0 + ty*8 + i;
        if (m >= M) continue;
#pragma unroll
        for (int j = 0; j < 8; j++) {
            int n = n0 + j*16 + tx;
            if (n >= N) continue;
            if (TOUT == 1) {
                float v = acc[i][j] + bias[n];
                if (RELU) v = fmaxf(v, 0.f);
                C[(size_t)m*ldc + n] = v;
            } else {
                float base = acc[i][j] + bias[n];
                float w = Bm[(size_t)n*ldb + K];
#pragma unroll
                for (int tt = 0; tt < TOUT; tt++)
                    C[(size_t)(m*TOUT + tt)*ldc + n] = base + (float)tt * w;
            }
        }
    }
}

// ================= attention (fp32 math, bf16-split output) =================
__global__ __launch_bounds__(256)
void attn_k(const float* __restrict__ qkv,
            __nv_bfloat16* __restrict__ oh, __nv_bfloat16* __restrict__ ol)
{
    int z = blockIdx.y;
    int bh = blockIdx.x;
    int b = bh / Hh, h = bh % Hh;
    __shared__ float ks[Sl][HD];
    __shared__ float vs[Sl][HD];
    int tid = threadIdx.x;
    const float* base = qkv + ((size_t)z*NTOK + (size_t)b*Sl)*(3*Dm);

    for (int e = tid; e < Sl*HD; e += 256) {
        int s = e / HD, d = e % HD;
        ks[s][d] = base[s*(3*Dm) + Dm   + h*HD + d];
        vs[s][d] = base[s*(3*Dm) + 2*Dm + h*HD + d];
    }
    __syncthreads();

    if (tid < Sl) {
        int s = tid;
        float q[HD];
#pragma unroll
        for (int d = 0; d < HD; d++)
            q[d] = base[s*(3*Dm) + h*HD + d] * 0.25f;

        float m = -1e30f, l = 0.f;
        float acc[HD];
#pragma unroll
        for (int d = 0; d < HD; d++) acc[d] = 0.f;

        for (int j = 0; j < Sl; j++) {
            float sc = 0.f;
#pragma unroll
            for (int d = 0; d < HD; d++) sc = fmaf(q[d], ks[j][d], sc);
            float nm  = fmaxf(m, sc);
            float cor = __expf(m - nm);
            float p   = __expf(sc - nm);
            l = l*cor + p;
#pragma unroll
            for (int d = 0; d < HD; d++) acc[d] = acc[d]*cor + p*vs[j][d];
            m = nm;
        }
        float inv = 1.f / l;
        size_t o = ((size_t)z*NTOK + (size_t)b*Sl + s)*Dm + h*HD;
#pragma unroll
        for (int d = 0; d < HD; d++) {
            float v = acc[d]*inv;
            __nv_bfloat16 hi = __float2bfloat16(v);
            oh[o + d] = hi;
            ol[o + d] = __float2bfloat16(v - __bfloat162float(hi));
        }
    }
}

// ========= fused residual-add + LayerNorm -> x(fp32) + xh/xl(bf16) =========
__global__ void add_ln_k(float* __restrict__ x, const float* __restrict__ r,
                         const float* __restrict__ g, const float* __restrict__ b,
                         size_t sW,
                         __nv_bfloat16* __restrict__ xh, __nv_bfloat16* __restrict__ xl)
{
    int z = blockIdx.y;
    int n = blockIdx.x, d = threadIdx.x;
    size_t tok = (size_t)z*NTOK + n;
    g += (size_t)z * sW;
    b += (size_t)z * sW;
    __shared__ float red[8];
    float v = x[tok*Dm + d] + r[tok*Dm + d];

    float s = v;
#pragma unroll
    for (int o = 16; o > 0; o >>= 1) s += __shfl_xor_sync(0xffffffffu, s, o);
    if ((d & 31) == 0) red[d >> 5] = s;
    __syncthreads();
    float mean = (red[0]+red[1]+red[2]+red[3]) * (1.f/Dm);

    float c = v - mean;
    float s2 = c*c;
#pragma unroll
    for (int o = 16; o > 0; o >>= 1) s2 += __shfl_xor_sync(0xffffffffu, s2, o);
    if ((d & 31) == 0) red[4 + (d >> 5)] = s2;
    __syncthreads();
    float var = (red[4]+red[5]+red[6]+red[7]) * (1.f/Dm);

    float y = c * rsqrtf(var + 1e-5f) * g[d] + b[d];
    x[tok*Dm + d] = y;
    __nv_bfloat16 hi = __float2bfloat16(y);
    xh[tok*Dm + d] = hi;
    xl[tok*Dm + d] = __float2bfloat16(y - __bfloat162float(hi));
}

__global__ void mean_k(const float* __restrict__ x, float* __restrict__ out)
{
    int z = blockIdx.y;
    int b = blockIdx.x, d = threadIdx.x;
    const float* xp = x + ((size_t)z*NTOK + (size_t)b*Sl)*Dm;
    float s = 0.f;
    for (int j = 0; j < Sl; j++) s += xp[j*Dm + d];
    out[b*(2*Dm) + z*Dm + d] = s * (1.f/Sl);
}

// ================= launcher =================
extern "C" void kernel_launch(void* const* d_in, const int* in_sizes, int n_in,
                              void* d_out, int out_size)
{
    const int*   tid_seq = (const int*)  d_in[0];
    const int*   iid_seq = (const int*)  d_in[1];
    const float* tab_emb = (const float*)d_in[2];
    const float* idx_emb = (const float*)d_in[3];
    const float* Wqkv = (const float*)d_in[4];
    const float* bqkv = (const float*)d_in[5];
    const float* Wo   = (const float*)d_in[6];
    const float* bo   = (const float*)d_in[7];
    const float* ln1g = (const float*)d_in[8];
    const float* ln1b = (const float*)d_in[9];
    const float* W1   = (const float*)d_in[10];
    const float* b1   = (const float*)d_in[11];
    const float* W2   = (const float*)d_in[12];
    const float* b2   = (const float*)d_in[13];
    const float* ln2g = (const float*)d_in[14];
    const float* ln2b = (const float*)d_in[15];
    const float* Wlin = (const float*)d_in[16];
    const float* blin = (const float*)d_in[17];
    const float* Wtab = (const float*)d_in[18];
    const float* btab = (const float*)d_in[19];
    const float* Widx = (const float*)d_in[20];
    const float* bidx = (const float*)d_in[21];

    float* out     = (float*)d_out;
    float* out_tab = out;
    float* out_idx = out + (size_t)Bz*TOUTN*TBLV;

    float *x, *qkv, *tmp, *hcat, *h;
    __nv_bfloat16 *xh, *xl, *ath, *atl, *ffh, *ffl;
    __nv_bfloat16 *Wqkvh, *Wqkvl, *Woh, *Wol, *W1h, *W1l, *W2h, *W2l;
    cudaGetSymbolAddress((void**)&x,    g_x);
    cudaGetSymbolAddress((void**)&qkv,  g_qkv);
    cudaGetSymbolAddress((void**)&tmp,  g_tmp);
    cudaGetSymbolAddress((void**)&hcat, g_hcat);
    cudaGetSymbolAddress((void**)&h,    g_h);
    cudaGetSymbolAddress((void**)&xh,   g_xh);
    cudaGetSymbolAddress((void**)&xl,   g_xl);
    cudaGetSymbolAddress((void**)&ath,  g_ath);
    cudaGetSymbolAddress((void**)&atl,  g_atl);
    cudaGetSymbolAddress((void**)&ffh,  g_ffh);
    cudaGetSymbolAddress((void**)&ffl,  g_ffl);
    cudaGetSymbolAddress((void**)&Wqkvh, g_Wqkvh);
    cudaGetSymbolAddress((void**)&Wqkvl, g_Wqkvl);
    cudaGetSymbolAddress((void**)&Woh,   g_Woh);
    cudaGetSymbolAddress((void**)&Wol,   g_Wol);
    cudaGetSymbolAddress((void**)&W1h,   g_W1h);
    cudaGetSymbolAddress((void**)&W1l,   g_W1l);
    cudaGetSymbolAddress((void**)&W2h,   g_W2h);
    cudaGetSymbolAddress((void**)&W2l,   g_W2l);

    const int MT = NTOK / 128;  // 200
    const size_t sX   = (size_t)NTOK*Dm;
    const size_t sQKV = (size_t)NTOK*3*Dm;
    const size_t sFF  = (size_t)NTOK*DFF;

    // weight split (hi/lo bf16)
    cvt_k<<<(2*Ll*3*Dm*Dm + 255)/256, 256>>>(Wqkv, Wqkvh, Wqkvl, 2*Ll*3*Dm*Dm);
    cvt_k<<<(2*Ll*Dm*Dm   + 255)/256, 256>>>(Wo,   Woh,   Wol,   2*Ll*Dm*Dm);
    cvt_k<<<(2*Ll*DFF*Dm  + 255)/256, 256>>>(W1,   W1h,   W1l,   2*Ll*DFF*Dm);
    cvt_k<<<(2*Ll*Dm*DFF  + 255)/256, 256>>>(W2,   W2h,   W2l,   2*Ll*Dm*DFF);

    embed2_k<<<dim3(NTOK, 2), Dm>>>(tid_seq, iid_seq, tab_emb, idx_emb, x, xh, xl);

    for (int l = 0; l < Ll; l++) {
        // qkv = x @ Wqkv^T + b
        gemm_mma<false,false><<<dim3(3, MT, 2), 256>>>(
            xh, xl, Dm, sX,
            Wqkvh + (size_t)l*3*Dm*Dm, Wqkvl + (size_t)l*3*Dm*Dm, Dm, (size_t)Ll*3*Dm*Dm,
            bqkv + (size_t)l*3*Dm, (size_t)Ll*3*Dm,
            qkv, nullptr, nullptr, 3*Dm, sQKV, Dm);

        attn_k<<<dim3(Bz*Hh, 2), 256>>>(qkv, ath, atl);

        // o proj
        gemm_mma<false,false><<<dim3(1, MT, 2), 256>>>(
            ath, atl, Dm, sX,
            Woh + (size_t)l*Dm*Dm, Wol + (size_t)l*Dm*Dm, Dm, (size_t)Ll*Dm*Dm,
            bo + (size_t)l*Dm, (size_t)Ll*Dm,
            tmp, nullptr, nullptr, Dm, sX, Dm);

        add_ln_k<<<dim3(NTOK, 2), Dm>>>(x, tmp, ln1g + (size_t)l*Dm, ln1b + (size_t)l*Dm,
                                        (size_t)Ll*Dm, xh, xl);

        // ff = relu(x @ W1^T + b1)  -> bf16 hi/lo
        gemm_mma<true,true><<<dim3(DFF/128, MT, 2), 256>>>(
            xh, xl, Dm, sX,
            W1h + (size_t)l*DFF*Dm, W1l + (size_t)l*DFF*Dm, Dm, (size_t)Ll*DFF*Dm,
            b1 + (size_t)l*DFF, (size_t)Ll*DFF,
            nullptr, ffh, ffl, DFF, sFF, Dm);

        // tmp = ff @ W2^T + b2
        gemm_mma<false,false><<<dim3(1, MT, 2), 256>>>(
            ffh, ffl, DFF, sFF,
            W2h + (size_t)l*Dm*DFF, W2l + (size_t)l*Dm*DFF, DFF, (size_t)Ll*Dm*DFF,
            b2 + (size_t)l*Dm, (size_t)Ll*Dm,
            tmp, nullptr, nullptr, Dm, sX, DFF);

        add_ln_k<<<dim3(NTOK, 2), Dm>>>(x, tmp, ln2g + (size_t)l*Dm, ln2b + (size_t)l*Dm,
                                        (size_t)Ll*Dm, xh, xl);
    }

    mean_k<<<dim3(Bz, 2), Dm>>>(x, hcat);

    // h = relu(hcat @ Wlin^T + blin)
    gemm_k<1,true><<<dim3(HID/128, 1), 256>>>(
        hcat, 2*Dm, Wlin, 2*Dm, blin, h, HID, Bz, HID, 2*Dm);

    // tab / idx: base + t-broadcast
    gemm_k<TOUTN,false><<<dim3((TBLV + 127)/128, 1), 256>>>(
        h, HID, Wtab, HID + 1, btab, out_tab, TBLV, Bz, TBLV, HID);
    gemm_k<TOUTN,false><<<dim3((IDXV + 127)/128, 1), 256>>>(
        h, HID, Widx, HID + 1, bidx, out_idx, IDXV, Bz, IDXV, HID);
}

// round 5
// speedup vs baseline: 1.5113x; 1.1674x over previous
#include <cuda_runtime.h>
#include <cuda_bf16.h>
#include <math.h>
#include <stdint.h>

#define Bz    128
#define Sl    200
#define Dm    128
#define Hh    8
#define HD    16
#define Ll    2
#define DFF   2048
#define HID   512
#define TBLV  1000
#define IDXV  100000
#define TOUTN 8
#define NTOK  (Bz*Sl)   // 25600

// ================= scratch (device globals) =================
__device__ float g_x   [2*NTOK*Dm];
__device__ float g_qkv [2*NTOK*3*Dm];
__device__ float g_tmp [2*NTOK*Dm];
__device__ float g_h   [Bz*HID];      // unused fp32 (kept for layout)
__device__ __nv_bfloat16 g_hcath[Bz*2*Dm], g_hcatl[Bz*2*Dm];
__device__ __nv_bfloat16 g_hh[Bz*HID],     g_hl[Bz*HID];
__device__ __nv_bfloat16 g_xh [2*NTOK*Dm];
__device__ __nv_bfloat16 g_xl [2*NTOK*Dm];
__device__ __nv_bfloat16 g_ath[2*NTOK*Dm];
__device__ __nv_bfloat16 g_atl[2*NTOK*Dm];
__device__ __nv_bfloat16 g_ffh[(size_t)2*NTOK*DFF];
__device__ __nv_bfloat16 g_ffl[(size_t)2*NTOK*DFF];
__device__ __nv_bfloat16 g_Wqkvh[2*Ll*3*Dm*Dm], g_Wqkvl[2*Ll*3*Dm*Dm];
__device__ __nv_bfloat16 g_Woh  [2*Ll*Dm*Dm],   g_Wol  [2*Ll*Dm*Dm];
__device__ __nv_bfloat16 g_W1h  [2*Ll*DFF*Dm],  g_W1l  [2*Ll*DFF*Dm];
__device__ __nv_bfloat16 g_W2h  [2*Ll*Dm*DFF],  g_W2l  [2*Ll*Dm*DFF];
__device__ __nv_bfloat16 g_Wlinh[HID*2*Dm],     g_Wlinl[HID*2*Dm];
__device__ __nv_bfloat16 g_Wtabh[TBLV*HID],     g_Wtabl[TBLV*HID];
__device__ float         g_wltab[TBLV];
__device__ __nv_bfloat16 g_Widxh[(size_t)IDXV*HID], g_Widxl[(size_t)IDXV*HID];
__device__ float         g_wlidx[IDXV];

// ================= mma helpers (baseline PTX, no sm_103a features) ==========
__device__ __forceinline__ uint32_t smem_u32(const void* p) {
    uint32_t a;
    asm("{ .reg .u64 t; cvta.to.shared.u64 t, %1; cvt.u32.u64 %0, t; }"
        : "=r"(a) : "l"(p));
    return a;
}
__device__ __forceinline__ void ldm_x4(uint32_t* r, uint32_t addr) {
    asm volatile("ldmatrix.sync.aligned.m8n8.x4.shared.b16 {%0,%1,%2,%3}, [%4];"
        : "=r"(r[0]), "=r"(r[1]), "=r"(r[2]), "=r"(r[3]) : "r"(addr));
}
__device__ __forceinline__ void mma16816(float* c, const uint32_t* a,
                                         uint32_t b0, uint32_t b1) {
    asm volatile("mma.sync.aligned.m16n8k16.row.col.f32.bf16.bf16.f32 "
        "{%0,%1,%2,%3}, {%4,%5,%6,%7}, {%8,%9}, {%0,%1,%2,%3};"
        : "+f"(c[0]), "+f"(c[1]), "+f"(c[2]), "+f"(c[3])
        : "r"(a[0]), "r"(a[1]), "r"(a[2]), "r"(a[3]), "r"(b0), "r"(b1));
}

// ================= small utility kernels =================
__global__ void cvt_k(const float* __restrict__ in, __nv_bfloat16* __restrict__ h,
                      __nv_bfloat16* __restrict__ l, int n)
{
    int i = blockIdx.x * 256 + threadIdx.x;
    if (i < n) {
        float v = in[i];
        __nv_bfloat16 hi = __float2bfloat16(v);
        h[i] = hi;
        l[i] = __float2bfloat16(v - __bfloat162float(hi));
    }
}

// repack W[V,513] -> hi/lo [V,512] + wlast[V]; thread handles 4 k values
__global__ void cvt_proj_k(const float* __restrict__ W, __nv_bfloat16* __restrict__ h,
                           __nv_bfloat16* __restrict__ l, float* __restrict__ wl, int V)
{
    int idx = blockIdx.x * 256 + threadIdx.x;
    int n  = idx >> 7;          // V rows, 128 thread-chunks/row
    int kc = idx & 127;
    if (n >= V) return;
    const float* src = W + (size_t)n * (HID + 1) + kc * 4;
    size_t dst = (size_t)n * HID + kc * 4;
#pragma unroll
    for (int j = 0; j < 4; j++) {
        float v = src[j];
        __nv_bfloat16 hi = __float2bfloat16(v);
        h[dst + j] = hi;
        l[dst + j] = __float2bfloat16(v - __bfloat162float(hi));
    }
    if (kc == 0) wl[n] = W[(size_t)n * (HID + 1) + HID];
}

__global__ void embed2_k(const int* __restrict__ ids0, const int* __restrict__ ids1,
                         const float* __restrict__ t0, const float* __restrict__ t1,
                         float* __restrict__ out,
                         __nv_bfloat16* __restrict__ oh, __nv_bfloat16* __restrict__ ol)
{
    int z = blockIdx.y, n = blockIdx.x, d = threadIdx.x;
    const int*   ids = z ? ids1 : ids0;
    const float* tab = z ? t1   : t0;
    size_t o = ((size_t)z*NTOK + n)*Dm + d;
    float v = tab[(size_t)ids[n]*Dm + d];
    out[o] = v;
    __nv_bfloat16 hi = __float2bfloat16(v);
    oh[o] = hi;
    ol[o] = __float2bfloat16(v - __bfloat162float(hi));
}

// ================= split-bf16 tensor-core GEMM ==============================
// C[M,N] = (Ah+Al)[M,K] @ (Bh+Bl)[N,K]^T + bias   (AlBl dropped, ~2^-18 rel)
// Block tile 128x128, stage BK=32, 8 warps (4x2), warp tile 32x64.
// smem: 4 tiles x 128 rows x 80B pitch (64B data + 16B pad), double-buffered
// = 80KB dynamic. ldmatrix conflict-free: row*5 mod 8 is a permutation.
// GUARD: clamp B rows / guard stores for N not multiple of 128.
// TOUT==8: time-broadcast epilogue using wl[n].
#define PITCH 80
#define TILEB (128*PITCH)
#define STAGEB (4*TILEB)
#define GSMEM (2*STAGEB)

template<int TOUT, bool RELU, bool OUTBF16, bool GUARD>
__global__ __launch_bounds__(256)
void gemm_mma(const __nv_bfloat16* __restrict__ Ah, const __nv_bfloat16* __restrict__ Al,
              int lda, size_t sA,
              const __nv_bfloat16* __restrict__ Bh, const __nv_bfloat16* __restrict__ Bl,
              int ldb, size_t sB,
              const float* __restrict__ bias, size_t sBias,
              const float* __restrict__ wl,
              float* __restrict__ Cf,
              __nv_bfloat16* __restrict__ Ch, __nv_bfloat16* __restrict__ Cl,
              int ldc, size_t sC, int N, int K)
{
    extern __shared__ __align__(16) char sm[];   // [2][4][TILEB]

    int tid  = threadIdx.x;
    int wid  = tid >> 5;
    int lane = tid & 31;
    int z = blockIdx.z;
    Ah += (size_t)z * sA;  Al += (size_t)z * sA;
    Bh += (size_t)z * sB;  Bl += (size_t)z * sB;
    bias += (size_t)z * sBias;
    if (OUTBF16) { Ch += (size_t)z * sC; Cl += (size_t)z * sC; }
    else         { Cf += (size_t)z * sC; }

    int m0 = blockIdx.y * 128;
    int n0 = blockIdx.x * 128;

    // ---- loader mapping: row = tid>>1, 2 chunks of 16B at (tid&1)*32 ----
    int lrow  = tid >> 1;
    int lhalf = tid & 1;
    int brow_g = GUARD ? min(n0 + lrow, N - 1) : (n0 + lrow);
    const __nv_bfloat16* pAh = Ah + (size_t)(m0 + lrow)*lda + lhalf*16;
    const __nv_bfloat16* pAl = Al + (size_t)(m0 + lrow)*lda + lhalf*16;
    const __nv_bfloat16* pBh = Bh + (size_t)brow_g*ldb + lhalf*16;
    const __nv_bfloat16* pBl = Bl + (size_t)brow_g*ldb + lhalf*16;
    int sdst = lrow*PITCH + lhalf*32;

    char* smA_h[2] = { sm,                     sm + STAGEB };
    char* smA_l[2] = { sm + TILEB,             sm + STAGEB + TILEB };
    char* smB_h[2] = { sm + 2*TILEB,           sm + STAGEB + 2*TILEB };
    char* smB_l[2] = { sm + 3*TILEB,           sm + STAGEB + 3*TILEB };

    // ---- compute mapping ----
    int wm = wid & 3;
    int wn = wid >> 2;
    int r8 = lane & 7, quad = lane >> 3;
    int arow = wm*32 + (quad & 1)*8 + r8;
    int aoff = (quad >> 1)*16;
    int brow = wn*64 + (quad >> 1)*8 + r8;
    int boff = (quad & 1)*16;

    float acc[2][8][4];
#pragma unroll
    for (int i = 0; i < 2; i++)
#pragma unroll
        for (int j = 0; j < 8; j++)
#pragma unroll
            for (int c = 0; c < 4; c++) acc[i][j][c] = 0.f;

    const int nst = K / 32;
    uint4 pf[8];

    // prologue: stage 0
#pragma unroll
    for (int c = 0; c < 2; c++) {
        pf[0+c] = *(const uint4*)(pAh + c*8);
        pf[2+c] = *(const uint4*)(pAl + c*8);
        pf[4+c] = *(const uint4*)(pBh + c*8);
        pf[6+c] = *(const uint4*)(pBl + c*8);
    }
#pragma unroll
    for (int c = 0; c < 2; c++) {
        *(uint4*)(smA_h[0] + sdst + c*16) = pf[0+c];
        *(uint4*)(smA_l[0] + sdst + c*16) = pf[2+c];
        *(uint4*)(smB_h[0] + sdst + c*16) = pf[4+c];
        *(uint4*)(smB_l[0] + sdst + c*16) = pf[6+c];
    }

    for (int it = 0; it < nst; ++it) {
        int buf = it & 1;
        bool more = (it + 1) < nst;
        if (more) {
            int k1 = (it + 1) * 32;
#pragma unroll
            for (int c = 0; c < 2; c++) {
                pf[0+c] = *(const uint4*)(pAh + k1 + c*8);
                pf[2+c] = *(const uint4*)(pAl + k1 + c*8);
                pf[4+c] = *(const uint4*)(pBh + k1 + c*8);
                pf[6+c] = *(const uint4*)(pBl + k1 + c*8);
            }
        }
        __syncthreads();

        uint32_t bAh = smem_u32(smA_h[buf]);
        uint32_t bAl = smem_u32(smA_l[buf]);
        uint32_t bBh = smem_u32(smB_h[buf]);
        uint32_t bBl = smem_u32(smB_l[buf]);

#pragma unroll
        for (int ks = 0; ks < 2; ks++) {
            int ko = ks * 32;
            uint32_t ah[2][4], al[2][4];
#pragma unroll
            for (int mi = 0; mi < 2; mi++) {
                ldm_x4(ah[mi], bAh + (arow + mi*16)*PITCH + ko + aoff);
                ldm_x4(al[mi], bAl + (arow + mi*16)*PITCH + ko + aoff);
            }
#pragma unroll
            for (int pj = 0; pj < 4; pj++) {
                uint32_t bh4[4], bl4[4];
                ldm_x4(bh4, bBh + (brow + pj*16)*PITCH + ko + boff);
                ldm_x4(bl4, bBl + (brow + pj*16)*PITCH + ko + boff);
#pragma unroll
                for (int mi = 0; mi < 2; mi++) {
                    mma16816(acc[mi][2*pj],   ah[mi], bh4[0], bh4[1]);
                    mma16816(acc[mi][2*pj+1], ah[mi], bh4[2], bh4[3]);
                    mma16816(acc[mi][2*pj],   al[mi], bh4[0], bh4[1]);
                    mma16816(acc[mi][2*pj+1], al[mi], bh4[2], bh4[3]);
                    mma16816(acc[mi][2*pj],   ah[mi], bl4[0], bl4[1]);
                    mma16816(acc[mi][2*pj+1], ah[mi], bl4[2], bl4[3]);
                }
            }
        }

        if (more) {
            int nb = buf ^ 1;
            __syncthreads();
#pragma unroll
            for (int c = 0; c < 2; c++) {
                *(uint4*)(smA_h[nb] + sdst + c*16) = pf[0+c];
                *(uint4*)(smA_l[nb] + sdst + c*16) = pf[2+c];
                *(uint4*)(smB_h[nb] + sdst + c*16) = pf[4+c];
                *(uint4*)(smB_l[nb] + sdst + c*16) = pf[6+c];
            }
        }
    }

    // ---- epilogue ----
    int mrow0 = m0 + wm*32 + (lane >> 2);
    int ncol0 = n0 + wn*64 + (lane & 3)*2;
#pragma unroll
    for (int mi = 0; mi < 2; mi++) {
#pragma unroll
        for (int nj = 0; nj < 8; nj++) {
            int col = ncol0 + nj*8;
            if (GUARD && col >= N) continue;
            float b0 = bias[col], b1 = bias[col + 1];
            float w0 = 0.f, w1 = 0.f;
            if (TOUT > 1) { w0 = wl[col]; w1 = wl[col + 1]; }
#pragma unroll
            for (int half = 0; half < 2; half++) {
                int row = mrow0 + mi*16 + half*8;
                float v0 = acc[mi][nj][2*half]     + b0;
                float v1 = acc[mi][nj][2*half + 1] + b1;
                if (RELU) { v0 = fmaxf(v0, 0.f); v1 = fmaxf(v1, 0.f); }
                if (TOUT > 1) {
#pragma unroll
                    for (int tt = 0; tt < TOUT; tt++) {
                        float2 v; v.x = v0 + tt*w0; v.y = v1 + tt*w1;
                        *(float2*)(Cf + (size_t)(row*TOUT + tt)*ldc + col) = v;
                    }
                } else if (OUTBF16) {
                    __nv_bfloat16 h0 = __float2bfloat16(v0);
                    __nv_bfloat16 h1 = __float2bfloat16(v1);
                    __nv_bfloat162 hp; hp.x = h0; hp.y = h1;
                    __nv_bfloat162 lp;
                    lp.x = __float2bfloat16(v0 - __bfloat162float(h0));
                    lp.y = __float2bfloat16(v1 - __bfloat162float(h1));
                    *(__nv_bfloat162*)(Ch + (size_t)row*ldc + col) = hp;
                    *(__nv_bfloat162*)(Cl + (size_t)row*ldc + col) = lp;
                } else {
                    float2 v; v.x = v0; v.y = v1;
                    *(float2*)(Cf + (size_t)row*ldc + col) = v;
                }
            }
        }
    }
}

// ================= attention (fp32 math, bf16-split output) =================
__global__ __launch_bounds__(256)
void attn_k(const float* __restrict__ qkv,
            __nv_bfloat16* __restrict__ oh, __nv_bfloat16* __restrict__ ol)
{
    int z = blockIdx.y;
    int bh = blockIdx.x;
    int b = bh / Hh, h = bh % Hh;
    __shared__ float ks[Sl][HD];
    __shared__ float vs[Sl][HD];
    int tid = threadIdx.x;
    const float* base = qkv + ((size_t)z*NTOK + (size_t)b*Sl)*(3*Dm);

    for (int e = tid; e < Sl*HD; e += 256) {
        int s = e / HD, d = e % HD;
        ks[s][d] = base[s*(3*Dm) + Dm   + h*HD + d];
        vs[s][d] = base[s*(3*Dm) + 2*Dm + h*HD + d];
    }
    __syncthreads();

    if (tid < Sl) {
        int s = tid;
        float q[HD];
#pragma unroll
        for (int d = 0; d < HD; d++)
            q[d] = base[s*(3*Dm) + h*HD + d] * 0.25f;

        float m = -1e30f, l = 0.f;
        float acc[HD];
#pragma unroll
        for (int d = 0; d < HD; d++) acc[d] = 0.f;

        for (int j = 0; j < Sl; j++) {
            float sc = 0.f;
#pragma unroll
            for (int d = 0; d < HD; d++) sc = fmaf(q[d], ks[j][d], sc);
            float nm  = fmaxf(m, sc);
            float cor = __expf(m - nm);
            float p   = __expf(sc - nm);
            l = l*cor + p;
#pragma unroll
            for (int d = 0; d < HD; d++) acc[d] = acc[d]*cor + p*vs[j][d];
            m = nm;
        }
        float inv = 1.f / l;
        size_t o = ((size_t)z*NTOK + (size_t)b*Sl + s)*Dm + h*HD;
#pragma unroll
        for (int d = 0; d < HD; d++) {
            float v = acc[d]*inv;
            __nv_bfloat16 hi = __float2bfloat16(v);
            oh[o + d] = hi;
            ol[o + d] = __float2bfloat16(v - __bfloat162float(hi));
        }
    }
}

// ========= fused residual-add + LayerNorm -> x(fp32) + xh/xl(bf16) =========
__global__ void add_ln_k(float* __restrict__ x, const float* __restrict__ r,
                         const float* __restrict__ g, const float* __restrict__ b,
                         size_t sW,
                         __nv_bfloat16* __restrict__ xh, __nv_bfloat16* __restrict__ xl)
{
    int z = blockIdx.y;
    int n = blockIdx.x, d = threadIdx.x;
    size_t tok = (size_t)z*NTOK + n;
    g += (size_t)z * sW;
    b += (size_t)z * sW;
    __shared__ float red[8];
    float v = x[tok*Dm + d] + r[tok*Dm + d];

    float s = v;
#pragma unroll
    for (int o = 16; o > 0; o >>= 1) s += __shfl_xor_sync(0xffffffffu, s, o);
    if ((d & 31) == 0) red[d >> 5] = s;
    __syncthreads();
    float mean = (red[0]+red[1]+red[2]+red[3]) * (1.f/Dm);

    float c = v - mean;
    float s2 = c*c;
#pragma unroll
    for (int o = 16; o > 0; o >>= 1) s2 += __shfl_xor_sync(0xffffffffu, s2, o);
    if ((d & 31) == 0) red[4 + (d >> 5)] = s2;
    __syncthreads();
    float var = (red[4]+red[5]+red[6]+red[7]) * (1.f/Dm);

    float y = c * rsqrtf(var + 1e-5f) * g[d] + b[d];
    x[tok*Dm + d] = y;
    __nv_bfloat16 hi = __float2bfloat16(y);
    xh[tok*Dm + d] = hi;
    xl[tok*Dm + d] = __float2bfloat16(y - __bfloat162float(hi));
}

// ---------------- sequence mean into split hcat --------------------------
__global__ void mean_k(const float* __restrict__ x,
                       __nv_bfloat16* __restrict__ oh, __nv_bfloat16* __restrict__ ol)
{
    int z = blockIdx.y;
    int b = blockIdx.x, d = threadIdx.x;
    const float* xp = x + ((size_t)z*NTOK + (size_t)b*Sl)*Dm;
    float s = 0.f;
    for (int j = 0; j < Sl; j++) s += xp[j*Dm + d];
    float v = s * (1.f/Sl);
    __nv_bfloat16 hi = __float2bfloat16(v);
    oh[b*(2*Dm) + z*Dm + d] = hi;
    ol[b*(2*Dm) + z*Dm + d] = __float2bfloat16(v - __bfloat162float(hi));
}

// ================= launcher =================
extern "C" void kernel_launch(void* const* d_in, const int* in_sizes, int n_in,
                              void* d_out, int out_size)
{
    const int*   tid_seq = (const int*)  d_in[0];
    const int*   iid_seq = (const int*)  d_in[1];
    const float* tab_emb = (const float*)d_in[2];
    const float* idx_emb = (const float*)d_in[3];
    const float* Wqkv = (const float*)d_in[4];
    const float* bqkv = (const float*)d_in[5];
    const float* Wo   = (const float*)d_in[6];
    const float* bo   = (const float*)d_in[7];
    const float* ln1g = (const float*)d_in[8];
    const float* ln1b = (const float*)d_in[9];
    const float* W1   = (const float*)d_in[10];
    const float* b1   = (const float*)d_in[11];
    const float* W2   = (const float*)d_in[12];
    const float* b2   = (const float*)d_in[13];
    const float* ln2g = (const float*)d_in[14];
    const float* ln2b = (const float*)d_in[15];
    const float* Wlin = (const float*)d_in[16];
    const float* blin = (const float*)d_in[17];
    const float* Wtab = (const float*)d_in[18];
    const float* btab = (const float*)d_in[19];
    const float* Widx = (const float*)d_in[20];
    const float* bidx = (const float*)d_in[21];

    float* out     = (float*)d_out;
    float* out_tab = out;
    float* out_idx = out + (size_t)Bz*TOUTN*TBLV;

    float *x, *qkv, *tmp;
    __nv_bfloat16 *xh, *xl, *ath, *atl, *ffh, *ffl;
    __nv_bfloat16 *hcath, *hcatl, *hh, *hl;
    __nv_bfloat16 *Wqkvh, *Wqkvl, *Woh, *Wol, *W1h, *W1l, *W2h, *W2l;
    __nv_bfloat16 *Wlinh, *Wlinl, *Wtabh, *Wtabl, *Widxh, *Widxl;
    float *wltab, *wlidx;
    cudaGetSymbolAddress((void**)&x,    g_x);
    cudaGetSymbolAddress((void**)&qkv,  g_qkv);
    cudaGetSymbolAddress((void**)&tmp,  g_tmp);
    cudaGetSymbolAddress((void**)&xh,   g_xh);
    cudaGetSymbolAddress((void**)&xl,   g_xl);
    cudaGetSymbolAddress((void**)&ath,  g_ath);
    cudaGetSymbolAddress((void**)&atl,  g_atl);
    cudaGetSymbolAddress((void**)&ffh,  g_ffh);
    cudaGetSymbolAddress((void**)&ffl,  g_ffl);
    cudaGetSymbolAddress((void**)&hcath, g_hcath);
    cudaGetSymbolAddress((void**)&hcatl, g_hcatl);
    cudaGetSymbolAddress((void**)&hh,   g_hh);
    cudaGetSymbolAddress((void**)&hl,   g_hl);
    cudaGetSymbolAddress((void**)&Wqkvh, g_Wqkvh);
    cudaGetSymbolAddress((void**)&Wqkvl, g_Wqkvl);
    cudaGetSymbolAddress((void**)&Woh,   g_Woh);
    cudaGetSymbolAddress((void**)&Wol,   g_Wol);
    cudaGetSymbolAddress((void**)&W1h,   g_W1h);
    cudaGetSymbolAddress((void**)&W1l,   g_W1l);
    cudaGetSymbolAddress((void**)&W2h,   g_W2h);
    cudaGetSymbolAddress((void**)&W2l,   g_W2l);
    cudaGetSymbolAddress((void**)&Wlinh, g_Wlinh);
    cudaGetSymbolAddress((void**)&Wlinl, g_Wlinl);
    cudaGetSymbolAddress((void**)&Wtabh, g_Wtabh);
    cudaGetSymbolAddress((void**)&Wtabl, g_Wtabl);
    cudaGetSymbolAddress((void**)&Widxh, g_Widxh);
    cudaGetSymbolAddress((void**)&Widxl, g_Widxl);
    cudaGetSymbolAddress((void**)&wltab, g_wltab);
    cudaGetSymbolAddress((void**)&wlidx, g_wlidx);

    cudaFuncSetAttribute(gemm_mma<1,false,false,false>, cudaFuncAttributeMaxDynamicSharedMemorySize, GSMEM);
    cudaFuncSetAttribute(gemm_mma<1,true, true, false>, cudaFuncAttributeMaxDynamicSharedMemorySize, GSMEM);
    cudaFuncSetAttribute(gemm_mma<TOUTN,false,false,true>, cudaFuncAttributeMaxDynamicSharedMemorySize, GSMEM);

    const int MT = NTOK / 128;  // 200
    const size_t sX   = (size_t)NTOK*Dm;
    const size_t sQKV = (size_t)NTOK*3*Dm;
    const size_t sFF  = (size_t)NTOK*DFF;

    // weight splits
    cvt_k<<<(2*Ll*3*Dm*Dm + 255)/256, 256>>>(Wqkv, Wqkvh, Wqkvl, 2*Ll*3*Dm*Dm);
    cvt_k<<<(2*Ll*Dm*Dm   + 255)/256, 256>>>(Wo,   Woh,   Wol,   2*Ll*Dm*Dm);
    cvt_k<<<(2*Ll*DFF*Dm  + 255)/256, 256>>>(W1,   W1h,   W1l,   2*Ll*DFF*Dm);
    cvt_k<<<(2*Ll*Dm*DFF  + 255)/256, 256>>>(W2,   W2h,   W2l,   2*Ll*Dm*DFF);
    cvt_k<<<(HID*2*Dm     + 255)/256, 256>>>(Wlin, Wlinh, Wlinl, HID*2*Dm);
    cvt_proj_k<<<(TBLV*128 + 255)/256, 256>>>(Wtab, Wtabh, Wtabl, wltab, TBLV);
    cvt_proj_k<<<(IDXV*128 + 255)/256, 256>>>(Widx, Widxh, Widxl, wlidx, IDXV);

    embed2_k<<<dim3(NTOK, 2), Dm>>>(tid_seq, iid_seq, tab_emb, idx_emb, x, xh, xl);

    for (int l = 0; l < Ll; l++) {
        // qkv = x @ Wqkv^T + b
        gemm_mma<1,false,false,false><<<dim3(3, MT, 2), 256, GSMEM>>>(
            xh, xl, Dm, sX,
            Wqkvh + (size_t)l*3*Dm*Dm, Wqkvl + (size_t)l*3*Dm*Dm, Dm, (size_t)Ll*3*Dm*Dm,
            bqkv + (size_t)l*3*Dm, (size_t)Ll*3*Dm, nullptr,
            qkv, nullptr, nullptr, 3*Dm, sQKV, 3*Dm, Dm);

        attn_k<<<dim3(Bz*Hh, 2), 256>>>(qkv, ath, atl);

        // o proj
        gemm_mma<1,false,false,false><<<dim3(1, MT, 2), 256, GSMEM>>>(
            ath, atl, Dm, sX,
            Woh + (size_t)l*Dm*Dm, Wol + (size_t)l*Dm*Dm, Dm, (size_t)Ll*Dm*Dm,
            bo + (size_t)l*Dm, (size_t)Ll*Dm, nullptr,
            tmp, nullptr, nullptr, Dm, sX, Dm, Dm);

        add_ln_k<<<dim3(NTOK, 2), Dm>>>(x, tmp, ln1g + (size_t)l*Dm, ln1b + (size_t)l*Dm,
                                        (size_t)Ll*Dm, xh, xl);

        // ff = relu(x @ W1^T + b1) -> bf16 hi/lo
        gemm_mma<1,true,true,false><<<dim3(DFF/128, MT, 2), 256, GSMEM>>>(
            xh, xl, Dm, sX,
            W1h + (size_t)l*DFF*Dm, W1l + (size_t)l*DFF*Dm, Dm, (size_t)Ll*DFF*Dm,
            b1 + (size_t)l*DFF, (size_t)Ll*DFF, nullptr,
            nullptr, ffh, ffl, DFF, sFF, DFF, Dm);

        // tmp = ff @ W2^T + b2
        gemm_mma<1,false,false,false><<<dim3(1, MT, 2), 256, GSMEM>>>(
            ffh, ffl, DFF, sFF,
            W2h + (size_t)l*Dm*DFF, W2l + (size_t)l*Dm*DFF, DFF, (size_t)Ll*Dm*DFF,
            b2 + (size_t)l*Dm, (size_t)Ll*Dm, nullptr,
            tmp, nullptr, nullptr, Dm, sX, Dm, DFF);

        add_ln_k<<<dim3(NTOK, 2), Dm>>>(x, tmp, ln2g + (size_t)l*Dm, ln2b + (size_t)l*Dm,
                                        (size_t)Ll*Dm, xh, xl);
    }

    mean_k<<<dim3(Bz, 2), Dm>>>(x, hcath, hcatl);

    // h = relu(hcat @ Wlin^T + blin) -> split   [128,512] K=256
    gemm_mma<1,true,true,false><<<dim3(HID/128, 1, 1), 256, GSMEM>>>(
        hcath, hcatl, 2*Dm, 0, Wlinh, Wlinl, 2*Dm, 0, blin, 0, nullptr,
        nullptr, hh, hl, HID, 0, HID, 2*Dm);

    // tab: [128,1000] + t-broadcast -> [1024,1000]
    gemm_mma<TOUTN,false,false,true><<<dim3((TBLV + 127)/128, 1, 1), 256, GSMEM>>>(
        hh, hl, HID, 0, Wtabh, Wtabl, HID, 0, btab, 0, wltab,
        out_tab, nullptr, nullptr, TBLV, 0, TBLV, HID);

    // idx: [128,100000] + t-broadcast -> [1024,100000]
    gemm_mma<TOUTN,false,false,true><<<dim3((IDXV + 127)/128, 1, 1), 256, GSMEM>>>(
        hh, hl, HID, 0, Widxh, Widxl, HID, 0, bidx, 0, wlidx,
        out_idx, nullptr, nullptr, IDXV, 0, IDXV, HID);
}

// round 7
// speedup vs baseline: 1.5669x; 1.0368x over previous
#include <cuda_runtime.h>
#include <cuda_bf16.h>
#include <math.h>
#include <stdint.h>

#define Bz    128
#define Sl    200
#define Dm    128
#define Hh    8
#define HD    16
#define Ll    2
#define DFF   2048
#define HID   512
#define TBLV  1000
#define IDXV  100000
#define TOUTN 8
#define NTOK  (Bz*Sl)   // 25600

// ================= scratch (device globals) =================
__device__ float g_x   [2*NTOK*Dm];
__device__ float g_qkv [2*NTOK*3*Dm];
__device__ float g_tmp [2*NTOK*Dm];
__device__ __nv_bfloat16 g_hcath[Bz*2*Dm], g_hcatl[Bz*2*Dm];
__device__ __nv_bfloat16 g_hh[Bz*HID],     g_hl[Bz*HID];
__device__ __nv_bfloat16 g_xh [2*NTOK*Dm];
__device__ __nv_bfloat16 g_xl [2*NTOK*Dm];
__device__ __nv_bfloat16 g_ath[2*NTOK*Dm];
__device__ __nv_bfloat16 g_atl[2*NTOK*Dm];
__device__ __nv_bfloat16 g_ffh[(size_t)2*NTOK*DFF];
__device__ __nv_bfloat16 g_ffl[(size_t)2*NTOK*DFF];
__device__ __nv_bfloat16 g_Wqkvh[2*Ll*3*Dm*Dm], g_Wqkvl[2*Ll*3*Dm*Dm];
__device__ __nv_bfloat16 g_Woh  [2*Ll*Dm*Dm],   g_Wol  [2*Ll*Dm*Dm];
__device__ __nv_bfloat16 g_W1h  [2*Ll*DFF*Dm],  g_W1l  [2*Ll*DFF*Dm];
__device__ __nv_bfloat16 g_W2h  [2*Ll*Dm*DFF],  g_W2l  [2*Ll*Dm*DFF];
__device__ __nv_bfloat16 g_Wlinh[HID*2*Dm],     g_Wlinl[HID*2*Dm];

// ================= asm helpers (baseline PTX only) ==========
__device__ __forceinline__ uint32_t smem_u32(const void* p) {
    uint32_t a;
    asm("{ .reg .u64 t; cvta.to.shared.u64 t, %1; cvt.u32.u64 %0, t; }"
        : "=r"(a) : "l"(p));
    return a;
}
__device__ __forceinline__ void ldm_x4(uint32_t* r, uint32_t addr) {
    asm volatile("ldmatrix.sync.aligned.m8n8.x4.shared.b16 {%0,%1,%2,%3}, [%4];"
        : "=r"(r[0]), "=r"(r[1]), "=r"(r[2]), "=r"(r[3]) : "r"(addr));
}
__device__ __forceinline__ void mma16816(float* c, const uint32_t* a,
                                         uint32_t b0, uint32_t b1) {
    asm volatile("mma.sync.aligned.m16n8k16.row.col.f32.bf16.bf16.f32 "
        "{%0,%1,%2,%3}, {%4,%5,%6,%7}, {%8,%9}, {%0,%1,%2,%3};"
        : "+f"(c[0]), "+f"(c[1]), "+f"(c[2]), "+f"(c[3])
        : "r"(a[0]), "r"(a[1]), "r"(a[2]), "r"(a[3]), "r"(b0), "r"(b1));
}
#define CP16(dst, src) \
    asm volatile("cp.async.cg.shared.global [%0], [%1], 16;" :: "r"(dst), "l"(src))
#define CP_COMMIT() asm volatile("cp.async.commit_group;" ::: "memory")
#define CP_WAIT1()  asm volatile("cp.async.wait_group 1;" ::: "memory")
#define CP_WAIT0()  asm volatile("cp.async.wait_group 0;" ::: "memory")

// ================= small utility kernels =================
__global__ void cvt_k(const float* __restrict__ in, __nv_bfloat16* __restrict__ h,
                      __nv_bfloat16* __restrict__ l, int n)
{
    int i = blockIdx.x * 256 + threadIdx.x;
    if (i < n) {
        float v = in[i];
        __nv_bfloat16 hi = __float2bfloat16(v);
        h[i] = hi;
        l[i] = __float2bfloat16(v - __bfloat162float(hi));
    }
}

__global__ void embed2_k(const int* __restrict__ ids0, const int* __restrict__ ids1,
                         const float* __restrict__ t0, const float* __restrict__ t1,
                         float* __restrict__ out,
                         __nv_bfloat16* __restrict__ oh, __nv_bfloat16* __restrict__ ol)
{
    int z = blockIdx.y, n = blockIdx.x, d = threadIdx.x;
    const int*   ids = z ? ids1 : ids0;
    const float* tab = z ? t1   : t0;
    size_t o = ((size_t)z*NTOK + n)*Dm + d;
    float v = tab[(size_t)ids[n]*Dm + d];
    out[o] = v;
    __nv_bfloat16 hi = __float2bfloat16(v);
    oh[o] = hi;
    ol[o] = __float2bfloat16(v - __bfloat162float(hi));
}

// ================= split-bf16 tensor-core GEMM ==============================
// C[M,N] = (Ah+Al)[M,K] @ (Bh+Bl)[N,K]^T + bias   (AlBl dropped)
// Block tile 128x128, stage BK=32, 8 warps (4x2), warp tile 32x64.
// CVTB=false: A/B bf16 hi/lo via 3-stage cp.async ring, 1 sync/stage. 120KB smem.
// CVTB=true : B is raw fp32 [N, ldb] (ldb=K+1 for projections); loader converts
//             to hi/lo on store. 2-stage reg path. Rows clamped, stores guarded.
// TOUT==8: time-broadcast epilogue, wlast = Bf[n*ldb + K].
#define PITCH  80
#define TILEB  (128*PITCH)
#define STAGEB (4*TILEB)
#define GSMEM3 (3*STAGEB)      // 122880
#define GSMEM2 (2*STAGEB)      // 81920

template<int TOUT, bool RELU, bool OUTBF16, bool CVTB>
__global__ __launch_bounds__(256)
void gemm_mma(const __nv_bfloat16* __restrict__ Ah, const __nv_bfloat16* __restrict__ Al,
              int lda, size_t sA,
              const __nv_bfloat16* __restrict__ Bh16, const __nv_bfloat16* __restrict__ Bl16,
              const float* __restrict__ Bf,
              int ldb, size_t sB,
              const float* __restrict__ bias, size_t sBias,
              float* __restrict__ Cf,
              __nv_bfloat16* __restrict__ Ch, __nv_bfloat16* __restrict__ Cl,
              int ldc, size_t sC, int N, int K)
{
    extern __shared__ __align__(16) char sm[];

    int tid  = threadIdx.x;
    int wid  = tid >> 5;
    int lane = tid & 31;
    int z = blockIdx.z;
    Ah += (size_t)z * sA;  Al += (size_t)z * sA;
    if (!CVTB) { Bh16 += (size_t)z * sB; Bl16 += (size_t)z * sB; }
    bias += (size_t)z * sBias;
    if (OUTBF16) { Ch += (size_t)z * sC; Cl += (size_t)z * sC; }
    else         { Cf += (size_t)z * sC; }

    int m0 = blockIdx.y * 128;
    int n0 = blockIdx.x * 128;

    int lrow  = tid >> 1;
    int lhalf = tid & 1;
    int sdst = lrow*PITCH + lhalf*32;
    uint32_t sbase = smem_u32(sm);

    // compute mapping
    int wm = wid & 3;
    int wn = wid >> 2;
    int r8 = lane & 7, quad = lane >> 3;
    int arow = wm*32 + (quad & 1)*8 + r8;
    int aoff = (quad >> 1)*16;
    int brow = wn*64 + (quad >> 1)*8 + r8;
    int boff = (quad & 1)*16;

    float acc[2][8][4];
#pragma unroll
    for (int i = 0; i < 2; i++)
#pragma unroll
        for (int j = 0; j < 8; j++)
#pragma unroll
            for (int c = 0; c < 4; c++) acc[i][j][c] = 0.f;

    const int nst = K / 32;

    if (!CVTB) {
        // ---------- 3-stage cp.async pipeline ----------
        const __nv_bfloat16* gAh = Ah + (size_t)(m0 + lrow)*lda + lhalf*16;
        const __nv_bfloat16* gAl = Al + (size_t)(m0 + lrow)*lda + lhalf*16;
        const __nv_bfloat16* gBh = Bh16 + (size_t)(n0 + lrow)*ldb + lhalf*16;
        const __nv_bfloat16* gBl = Bl16 + (size_t)(n0 + lrow)*ldb + lhalf*16;

#define ISSUE(s) do { \
        uint32_t st_ = sbase + ((s) % 3)*STAGEB + sdst; \
        int k0_ = (s)*32; \
        CP16(st_,              gAh + k0_); CP16(st_ + 16,             gAh + k0_ + 8); \
        CP16(st_ +   TILEB,    gAl + k0_); CP16(st_ +   TILEB + 16,   gAl + k0_ + 8); \
        CP16(st_ + 2*TILEB,    gBh + k0_); CP16(st_ + 2*TILEB + 16,   gBh + k0_ + 8); \
        CP16(st_ + 3*TILEB,    gBl + k0_); CP16(st_ + 3*TILEB + 16,   gBl + k0_ + 8); \
        CP_COMMIT(); } while (0)

        ISSUE(0);
        if (nst > 1) ISSUE(1);

        for (int it = 0; it < nst; ++it) {
            if (it + 1 < nst) { CP_WAIT1(); } else { CP_WAIT0(); }
            __syncthreads();
            if (it + 2 < nst) ISSUE(it + 2);

            uint32_t stb = sbase + (it % 3)*STAGEB;
            uint32_t bAh = stb;
            uint32_t bAl = stb + TILEB;
            uint32_t bBh = stb + 2*TILEB;
            uint32_t bBl = stb + 3*TILEB;
#pragma unroll
            for (int ks = 0; ks < 2; ks++) {
                int ko = ks * 32;
                uint32_t ah[2][4], al[2][4];
#pragma unroll
                for (int mi = 0; mi < 2; mi++) {
                    ldm_x4(ah[mi], bAh + (arow + mi*16)*PITCH + ko + aoff);
                    ldm_x4(al[mi], bAl + (arow + mi*16)*PITCH + ko + aoff);
                }
#pragma unroll
                for (int pj = 0; pj < 4; pj++) {
                    uint32_t bh4[4], bl4[4];
                    ldm_x4(bh4, bBh + (brow + pj*16)*PITCH + ko + boff);
                    ldm_x4(bl4, bBl + (brow + pj*16)*PITCH + ko + boff);
#pragma unroll
                    for (int mi = 0; mi < 2; mi++) {
                        mma16816(acc[mi][2*pj],   ah[mi], bh4[0], bh4[1]);
                        mma16816(acc[mi][2*pj+1], ah[mi], bh4[2], bh4[3]);
                        mma16816(acc[mi][2*pj],   al[mi], bh4[0], bh4[1]);
                        mma16816(acc[mi][2*pj+1], al[mi], bh4[2], bh4[3]);
                        mma16816(acc[mi][2*pj],   ah[mi], bl4[0], bl4[1]);
                        mma16816(acc[mi][2*pj+1], ah[mi], bl4[2], bl4[3]);
                    }
                }
            }
        }
#undef ISSUE
    } else {
        // ---------- 2-stage register path, B fp32 converted on store ----------
        int browg = min(n0 + lrow, N - 1);
        const __nv_bfloat16* gAh = Ah + (size_t)(m0 + lrow)*lda + lhalf*16;
        const __nv_bfloat16* gAl = Al + (size_t)(m0 + lrow)*lda + lhalf*16;
        const float* gB = Bf + (size_t)browg*ldb + lhalf*16;

        uint4 pa0, pa1, pa2, pa3;        // full 32B per thread for Ah and Al
        uint32_t pbh[8], pbl[8];

        auto loadstage = [&](int k0) {
            pa0 = *(const uint4*)(gAh + k0);
            pa1 = *(const uint4*)(gAh + k0 + 8);
            pa2 = *(const uint4*)(gAl + k0);
            pa3 = *(const uint4*)(gAl + k0 + 8);
#pragma unroll
            for (int j = 0; j < 8; j++) {
                float v0 = gB[k0 + 2*j];
                float v1 = gB[k0 + 2*j + 1];
                __nv_bfloat16 h0 = __float2bfloat16(v0);
                __nv_bfloat16 h1 = __float2bfloat16(v1);
                __nv_bfloat162 hp; hp.x = h0; hp.y = h1;
                __nv_bfloat162 lp;
                lp.x = __float2bfloat16(v0 - __bfloat162float(h0));
                lp.y = __float2bfloat16(v1 - __bfloat162float(h1));
                pbh[j] = *(uint32_t*)&hp;
                pbl[j] = *(uint32_t*)&lp;
            }
        };
        auto storestage = [&](int b) {
            char* stg = sm + b*STAGEB;
            *(uint4*)(stg + sdst)                = pa0;
            *(uint4*)(stg + sdst + 16)           = pa1;
            *(uint4*)(stg + TILEB + sdst)        = pa2;
            *(uint4*)(stg + TILEB + sdst + 16)   = pa3;
            *(uint4*)(stg + 2*TILEB + sdst)      = make_uint4(pbh[0],pbh[1],pbh[2],pbh[3]);
            *(uint4*)(stg + 2*TILEB + sdst + 16) = make_uint4(pbh[4],pbh[5],pbh[6],pbh[7]);
            *(uint4*)(stg + 3*TILEB + sdst)      = make_uint4(pbl[0],pbl[1],pbl[2],pbl[3]);
            *(uint4*)(stg + 3*TILEB + sdst + 16) = make_uint4(pbl[4],pbl[5],pbl[6],pbl[7]);
        };

        loadstage(0);
        storestage(0);

        for (int it = 0; it < nst; ++it) {
            int buf = it & 1;
            bool more = (it + 1) < nst;
            if (more) loadstage((it + 1) * 32);
            __syncthreads();

            uint32_t stb = sbase + buf*STAGEB;
            uint32_t bAh = stb;
            uint32_t bAl = stb + TILEB;
            uint32_t bBh = stb + 2*TILEB;
            uint32_t bBl = stb + 3*TILEB;
#pragma unroll
            for (int ks = 0; ks < 2; ks++) {
                int ko = ks * 32;
                uint32_t ah[2][4], al[2][4];
#pragma unroll
                for (int mi = 0; mi < 2; mi++) {
                    ldm_x4(ah[mi], bAh + (arow + mi*16)*PITCH + ko + aoff);
                    ldm_x4(al[mi], bAl + (arow + mi*16)*PITCH + ko + aoff);
                }
#pragma unroll
                for (int pj = 0; pj < 4; pj++) {
                    uint32_t bh4[4], bl4[4];
                    ldm_x4(bh4, bBh + (brow + pj*16)*PITCH + ko + boff);
                    ldm_x4(bl4, bBl + (brow + pj*16)*PITCH + ko + boff);
#pragma unroll
                    for (int mi = 0; mi < 2; mi++) {
                        mma16816(acc[mi][2*pj],   ah[mi], bh4[0], bh4[1]);
                        mma16816(acc[mi][2*pj+1], ah[mi], bh4[2], bh4[3]);
                        mma16816(acc[mi][2*pj],   al[mi], bh4[0], bh4[1]);
                        mma16816(acc[mi][2*pj+1], al[mi], bh4[2], bh4[3]);
                        mma16816(acc[mi][2*pj],   ah[mi], bl4[0], bl4[1]);
                        mma16816(acc[mi][2*pj+1], ah[mi], bl4[2], bl4[3]);
                    }
                }
            }

            if (more) {
                __syncthreads();
                storestage(buf ^ 1);
            }
        }
    }

    // ---- epilogue ----
    int mrow0 = m0 + wm*32 + (lane >> 2);
    int ncol0 = n0 + wn*64 + (lane & 3)*2;
#pragma unroll
    for (int mi = 0; mi < 2; mi++) {
#pragma unroll
        for (int nj = 0; nj < 8; nj++) {
            int col = ncol0 + nj*8;
            if (CVTB && col >= N) continue;
            float b0 = bias[col], b1 = bias[col + 1];
            float w0 = 0.f, w1 = 0.f;
            if (TOUT > 1) {
                w0 = Bf[(size_t)col*ldb + K];
                w1 = Bf[(size_t)(col + 1)*ldb + K];
            }
#pragma unroll
            for (int half = 0; half < 2; half++) {
                int row = mrow0 + mi*16 + half*8;
                float v0 = acc[mi][nj][2*half]     + b0;
                float v1 = acc[mi][nj][2*half + 1] + b1;
                if (RELU) { v0 = fmaxf(v0, 0.f); v1 = fmaxf(v1, 0.f); }
                if (TOUT > 1) {
#pragma unroll
                    for (int tt = 0; tt < TOUT; tt++) {
                        float2 v; v.x = v0 + tt*w0; v.y = v1 + tt*w1;
                        *(float2*)(Cf + (size_t)(row*TOUT + tt)*ldc + col) = v;
                    }
                } else if (OUTBF16) {
                    __nv_bfloat16 h0 = __float2bfloat16(v0);
                    __nv_bfloat16 h1 = __float2bfloat16(v1);
                    __nv_bfloat162 hp; hp.x = h0; hp.y = h1;
                    __nv_bfloat162 lp;
                    lp.x = __float2bfloat16(v0 - __bfloat162float(h0));
                    lp.y = __float2bfloat16(v1 - __bfloat162float(h1));
                    *(__nv_bfloat162*)(Ch + (size_t)row*ldc + col) = hp;
                    *(__nv_bfloat162*)(Cl + (size_t)row*ldc + col) = lp;
                } else {
                    float2 v; v.x = v0; v.y = v1;
                    *(float2*)(Cf + (size_t)row*ldc + col) = v;
                }
            }
        }
    }
}

// ================= attention (fp32 math, bf16-split output) =================
__global__ __launch_bounds__(256)
void attn_k(const float* __restrict__ qkv,
            __nv_bfloat16* __restrict__ oh, __nv_bfloat16* __restrict__ ol)
{
    int z = blockIdx.y;
    int bh = blockIdx.x;
    int b = bh / Hh, h = bh % Hh;
    __shared__ float ks[Sl][HD];
    __shared__ float vs[Sl][HD];
    int tid = threadIdx.x;
    const float* base = qkv + ((size_t)z*NTOK + (size_t)b*Sl)*(3*Dm);

    for (int e = tid; e < Sl*HD; e += 256) {
        int s = e / HD, d = e % HD;
        ks[s][d] = base[s*(3*Dm) + Dm   + h*HD + d];
        vs[s][d] = base[s*(3*Dm) + 2*Dm + h*HD + d];
    }
    __syncthreads();

    if (tid < Sl) {
        int s = tid;
        float q[HD];
#pragma unroll
        for (int d = 0; d < HD; d++)
            q[d] = base[s*(3*Dm) + h*HD + d] * 0.25f;

        float m = -1e30f, l = 0.f;
        float acc[HD];
#pragma unroll
        for (int d = 0; d < HD; d++) acc[d] = 0.f;

        for (int j = 0; j < Sl; j++) {
            float sc = 0.f;
#pragma unroll
            for (int d = 0; d < HD; d++) sc = fmaf(q[d], ks[j][d], sc);
            float nm  = fmaxf(m, sc);
            float cor = __expf(m - nm);
            float p   = __expf(sc - nm);
            l = l*cor + p;
#pragma unroll
            for (int d = 0; d < HD; d++) acc[d] = acc[d]*cor + p*vs[j][d];
            m = nm;
        }
        float inv = 1.f / l;
        size_t o = ((size_t)z*NTOK + (size_t)b*Sl + s)*Dm + h*HD;
#pragma unroll
        for (int d = 0; d < HD; d++) {
            float v = acc[d]*inv;
            __nv_bfloat16 hi = __float2bfloat16(v);
            oh[o + d] = hi;
            ol[o + d] = __float2bfloat16(v - __bfloat162float(hi));
        }
    }
}

// ========= fused residual-add + LayerNorm -> x(fp32) + xh/xl(bf16) =========
__global__ void add_ln_k(float* __restrict__ x, const float* __restrict__ r,
                         const float* __restrict__ g, const float* __restrict__ b,
                         size_t sW,
                         __nv_bfloat16* __restrict__ xh, __nv_bfloat16* __restrict__ xl)
{
    int z = blockIdx.y;
    int n = blockIdx.x, d = threadIdx.x;
    size_t tok = (size_t)z*NTOK + n;
    g += (size_t)z * sW;
    b += (size_t)z * sW;
    __shared__ float red[8];
    float v = x[tok*Dm + d] + r[tok*Dm + d];

    float s = v;
#pragma unroll
    for (int o = 16; o > 0; o >>= 1) s += __shfl_xor_sync(0xffffffffu, s, o);
    if ((d & 31) == 0) red[d >> 5] = s;
    __syncthreads();
    float mean = (red[0]+red[1]+red[2]+red[3]) * (1.f/Dm);

    float c = v - mean;
    float s2 = c*c;
#pragma unroll
    for (int o = 16; o > 0; o >>= 1) s2 += __shfl_xor_sync(0xffffffffu, s2, o);
    if ((d & 31) == 0) red[4 + (d >> 5)] = s2;
    __syncthreads();
    float var = (red[4]+red[5]+red[6]+red[7]) * (1.f/Dm);

    float y = c * rsqrtf(var + 1e-5f) * g[d] + b[d];
    x[tok*Dm + d] = y;
    __nv_bfloat16 hi = __float2bfloat16(y);
    xh[tok*Dm + d] = hi;
    xl[tok*Dm + d] = __float2bfloat16(y - __bfloat162float(hi));
}

// ---------------- sequence mean into split hcat --------------------------
__global__ void mean_k(const float* __restrict__ x,
                       __nv_bfloat16* __restrict__ oh, __nv_bfloat16* __restrict__ ol)
{
    int z = blockIdx.y;
    int b = blockIdx.x, d = threadIdx.x;
    const float* xp = x + ((size_t)z*NTOK + (size_t)b*Sl)*Dm;
    float s = 0.f;
    for (int j = 0; j < Sl; j++) s += xp[j*Dm + d];
    float v = s * (1.f/Sl);
    __nv_bfloat16 hi = __float2bfloat16(v);
    oh[b*(2*Dm) + z*Dm + d] = hi;
    ol[b*(2*Dm) + z*Dm + d] = __float2bfloat16(v - __bfloat162float(hi));
}

// ================= launcher =================
extern "C" void kernel_launch(void* const* d_in, const int* in_sizes, int n_in,
                              void* d_out, int out_size)
{
    const int*   tid_seq = (const int*)  d_in[0];
    const int*   iid_seq = (const int*)  d_in[1];
    const float* tab_emb = (const float*)d_in[2];
    const float* idx_emb = (const float*)d_in[3];
    const float* Wqkv = (const float*)d_in[4];
    const float* bqkv = (const float*)d_in[5];
    const float* Wo   = (const float*)d_in[6];
    const float* bo   = (const float*)d_in[7];
    const float* ln1g = (const float*)d_in[8];
    const float* ln1b = (const float*)d_in[9];
    const float* W1   = (const float*)d_in[10];
    const float* b1   = (const float*)d_in[11];
    const float* W2   = (const float*)d_in[12];
    const float* b2   = (const float*)d_in[13];
    const float* ln2g = (const float*)d_in[14];
    const float* ln2b = (const float*)d_in[15];
    const float* Wlin = (const float*)d_in[16];
    const float* blin = (const float*)d_in[17];
    const float* Wtab = (const float*)d_in[18];
    const float* btab = (const float*)d_in[19];
    const float* Widx = (const float*)d_in[20];
    const float* bidx = (const float*)d_in[21];

    float* out     = (float*)d_out;
    float* out_tab = out;
    float* out_idx = out + (size_t)Bz*TOUTN*TBLV;

    float *x, *qkv, *tmp;
    __nv_bfloat16 *xh, *xl, *ath, *atl, *ffh, *ffl;
    __nv_bfloat16 *hcath, *hcatl, *hh, *hl;
    __nv_bfloat16 *Wqkvh, *Wqkvl, *Woh, *Wol, *W1h, *W1l, *W2h, *W2l;
    __nv_bfloat16 *Wlinh, *Wlinl;
    cudaGetSymbolAddress((void**)&x,    g_x);
    cudaGetSymbolAddress((void**)&qkv,  g_qkv);
    cudaGetSymbolAddress((void**)&tmp,  g_tmp);
    cudaGetSymbolAddress((void**)&xh,   g_xh);
    cudaGetSymbolAddress((void**)&xl,   g_xl);
    cudaGetSymbolAddress((void**)&ath,  g_ath);
    cudaGetSymbolAddress((void**)&atl,  g_atl);
    cudaGetSymbolAddress((void**)&ffh,  g_ffh);
    cudaGetSymbolAddress((void**)&ffl,  g_ffl);
    cudaGetSymbolAddress((void**)&hcath, g_hcath);
    cudaGetSymbolAddress((void**)&hcatl, g_hcatl);
    cudaGetSymbolAddress((void**)&hh,   g_hh);
    cudaGetSymbolAddress((void**)&hl,   g_hl);
    cudaGetSymbolAddress((void**)&Wqkvh, g_Wqkvh);
    cudaGetSymbolAddress((void**)&Wqkvl, g_Wqkvl);
    cudaGetSymbolAddress((void**)&Woh,   g_Woh);
    cudaGetSymbolAddress((void**)&Wol,   g_Wol);
    cudaGetSymbolAddress((void**)&W1h,   g_W1h);
    cudaGetSymbolAddress((void**)&W1l,   g_W1l);
    cudaGetSymbolAddress((void**)&W2h,   g_W2h);
    cudaGetSymbolAddress((void**)&W2l,   g_W2l);
    cudaGetSymbolAddress((void**)&Wlinh, g_Wlinh);
    cudaGetSymbolAddress((void**)&Wlinl, g_Wlinl);

    cudaFuncSetAttribute(gemm_mma<1,false,false,false>, cudaFuncAttributeMaxDynamicSharedMemorySize, GSMEM3);
    cudaFuncSetAttribute(gemm_mma<1,true, true, false>, cudaFuncAttributeMaxDynamicSharedMemorySize, GSMEM3);
    cudaFuncSetAttribute(gemm_mma<TOUTN,false,false,true>, cudaFuncAttributeMaxDynamicSharedMemorySize, GSMEM2);

    const int MT = NTOK / 128;  // 200
    const size_t sX   = (size_t)NTOK*Dm;
    const size_t sQKV = (size_t)NTOK*3*Dm;
    const size_t sFF  = (size_t)NTOK*DFF;

    // weight splits (encoder + Wlin only; projections convert in-kernel)
    cvt_k<<<(2*Ll*3*Dm*Dm + 255)/256, 256>>>(Wqkv, Wqkvh, Wqkvl, 2*Ll*3*Dm*Dm);
    cvt_k<<<(2*Ll*Dm*Dm   + 255)/256, 256>>>(Wo,   Woh,   Wol,   2*Ll*Dm*Dm);
    cvt_k<<<(2*Ll*DFF*Dm  + 255)/256, 256>>>(W1,   W1h,   W1l,   2*Ll*DFF*Dm);
    cvt_k<<<(2*Ll*Dm*DFF  + 255)/256, 256>>>(W2,   W2h,   W2l,   2*Ll*Dm*DFF);
    cvt_k<<<(HID*2*Dm     + 255)/256, 256>>>(Wlin, Wlinh, Wlinl, HID*2*Dm);

    embed2_k<<<dim3(NTOK, 2), Dm>>>(tid_seq, iid_seq, tab_emb, idx_emb, x, xh, xl);

    for (int l = 0; l < Ll; l++) {
        // qkv = x @ Wqkv^T + b
        gemm_mma<1,false,false,false><<<dim3(3, MT, 2), 256, GSMEM3>>>(
            xh, xl, Dm, sX,
            Wqkvh + (size_t)l*3*Dm*Dm, Wqkvl + (size_t)l*3*Dm*Dm, nullptr,
            Dm, (size_t)Ll*3*Dm*Dm,
            bqkv + (size_t)l*3*Dm, (size_t)Ll*3*Dm,
            qkv, nullptr, nullptr, 3*Dm, sQKV, 3*Dm, Dm);

        attn_k<<<dim3(Bz*Hh, 2), 256>>>(qkv, ath, atl);

        // o proj
        gemm_mma<1,false,false,false><<<dim3(1, MT, 2), 256, GSMEM3>>>(
            ath, atl, Dm, sX,
            Woh + (size_t)l*Dm*Dm, Wol + (size_t)l*Dm*Dm, nullptr,
            Dm, (size_t)Ll*Dm*Dm,
            bo + (size_t)l*Dm, (size_t)Ll*Dm,
            tmp, nullptr, nullptr, Dm, sX, Dm, Dm);

        add_ln_k<<<dim3(NTOK, 2), Dm>>>(x, tmp, ln1g + (size_t)l*Dm, ln1b + (size_t)l*Dm,
                                        (size_t)Ll*Dm, xh, xl);

        // ff = relu(x @ W1^T + b1) -> bf16 hi/lo
        gemm_mma<1,true,true,false><<<dim3(DFF/128, MT, 2), 256, GSMEM3>>>(
            xh, xl, Dm, sX,
            W1h + (size_t)l*DFF*Dm, W1l + (size_t)l*DFF*Dm, nullptr,
            Dm, (size_t)Ll*DFF*Dm,
            b1 + (size_t)l*DFF, (size_t)Ll*DFF,
            nullptr, ffh, ffl, DFF, sFF, DFF, Dm);

        // tmp = ff @ W2^T + b2
        gemm_mma<1,false,false,false><<<dim3(1, MT, 2), 256, GSMEM3>>>(
            ffh, ffl, DFF, sFF,
            W2h + (size_t)l*Dm*DFF, W2l + (size_t)l*Dm*DFF, nullptr,
            DFF, (size_t)Ll*Dm*DFF,
            b2 + (size_t)l*Dm, (size_t)Ll*Dm,
            tmp, nullptr, nullptr, Dm, sX, Dm, DFF);

        add_ln_k<<<dim3(NTOK, 2), Dm>>>(x, tmp, ln2g + (size_t)l*Dm, ln2b + (size_t)l*Dm,
                                        (size_t)Ll*Dm, xh, xl);
    }

    mean_k<<<dim3(Bz, 2), Dm>>>(x, hcath, hcatl);

    // h = relu(hcat @ Wlin^T + blin) -> split   [128,512] K=256
    gemm_mma<1,true,true,false><<<dim3(HID/128, 1, 1), 256, GSMEM3>>>(
        hcath, hcatl, 2*Dm, 0, Wlinh, Wlinl, nullptr, 2*Dm, 0, blin, 0,
        nullptr, hh, hl, HID, 0, HID, 2*Dm);

    // tab: [128,1000] + t-broadcast -> [1024,1000]  (fp32 W converted in-kernel)
    gemm_mma<TOUTN,false,false,true><<<dim3((TBLV + 127)/128, 1, 1), 256, GSMEM2>>>(
        hh, hl, HID, 0, nullptr, nullptr, Wtab, HID + 1, 0, btab, 0,
        out_tab, nullptr, nullptr, TBLV, 0, TBLV, HID);

    // idx: [128,100000] + t-broadcast -> [1024,100000]
    gemm_mma<TOUTN,false,false,true><<<dim3((IDXV + 127)/128, 1, 1), 256, GSMEM2>>>(
        hh, hl, HID, 0, nullptr, nullptr, Widx, HID + 1, 0, bidx, 0,
        out_idx, nullptr, nullptr, IDXV, 0, IDXV, HID);
}

// round 8
// speedup vs baseline: 1.7939x; 1.1449x over previous
#include <cuda_runtime.h>
#include <cuda_bf16.h>
#include <math.h>
#include <stdint.h>

#define Bz    128
#define Sl    200
#define Dm    128
#define Hh    8
#define HD    16
#define Ll    2
#define DFF   2048
#define HID   512
#define TBLV  1000
#define IDXV  100000
#define TOUTN 8
#define NTOK  (Bz*Sl)   // 25600

// ================= scratch (device globals) =================
__device__ float g_x   [2*NTOK*Dm];
__device__ float g_qkv [2*NTOK*3*Dm];
__device__ float g_tmp [2*NTOK*Dm];
__device__ __nv_bfloat16 g_hcath[Bz*2*Dm], g_hcatl[Bz*2*Dm];
__device__ __nv_bfloat16 g_hh[Bz*HID],     g_hl[Bz*HID];
__device__ __nv_bfloat16 g_xh [2*NTOK*Dm];
__device__ __nv_bfloat16 g_xl [2*NTOK*Dm];
__device__ __nv_bfloat16 g_ath[2*NTOK*Dm];
__device__ __nv_bfloat16 g_atl[2*NTOK*Dm];
__device__ __nv_bfloat16 g_ffh[(size_t)2*NTOK*DFF];
__device__ __nv_bfloat16 g_ffl[(size_t)2*NTOK*DFF];
__device__ __nv_bfloat16 g_Wqkvh[2*Ll*3*Dm*Dm], g_Wqkvl[2*Ll*3*Dm*Dm];
__device__ __nv_bfloat16 g_Woh  [2*Ll*Dm*Dm],   g_Wol  [2*Ll*Dm*Dm];
__device__ __nv_bfloat16 g_W1h  [2*Ll*DFF*Dm],  g_W1l  [2*Ll*DFF*Dm];
__device__ __nv_bfloat16 g_W2h  [2*Ll*Dm*DFF],  g_W2l  [2*Ll*Dm*DFF];
__device__ __nv_bfloat16 g_Wlinh[HID*2*Dm],     g_Wlinl[HID*2*Dm];

// ================= asm helpers (baseline PTX only) ==========
__device__ __forceinline__ uint32_t smem_u32(const void* p) {
    uint32_t a;
    asm("{ .reg .u64 t; cvta.to.shared.u64 t, %1; cvt.u32.u64 %0, t; }"
        : "=r"(a) : "l"(p));
    return a;
}
__device__ __forceinline__ void ldm_x4(uint32_t* r, uint32_t addr) {
    asm volatile("ldmatrix.sync.aligned.m8n8.x4.shared.b16 {%0,%1,%2,%3}, [%4];"
        : "=r"(r[0]), "=r"(r[1]), "=r"(r[2]), "=r"(r[3]) : "r"(addr));
}
__device__ __forceinline__ void mma16816(float* c, const uint32_t* a,
                                         uint32_t b0, uint32_t b1) {
    asm volatile("mma.sync.aligned.m16n8k16.row.col.f32.bf16.bf16.f32 "
        "{%0,%1,%2,%3}, {%4,%5,%6,%7}, {%8,%9}, {%0,%1,%2,%3};"
        : "+f"(c[0]), "+f"(c[1]), "+f"(c[2]), "+f"(c[3])
        : "r"(a[0]), "r"(a[1]), "r"(a[2]), "r"(a[3]), "r"(b0), "r"(b1));
}
#define CP16(dst, src) \
    asm volatile("cp.async.cg.shared.global [%0], [%1], 16;" :: "r"(dst), "l"(src))
#define CP_COMMIT() asm volatile("cp.async.commit_group;" ::: "memory")
#define CP_WAIT0()  asm volatile("cp.async.wait_group 0;" ::: "memory")

// ================= small utility kernels =================
__global__ void cvt_k(const float* __restrict__ in, __nv_bfloat16* __restrict__ h,
                      __nv_bfloat16* __restrict__ l, int n)
{
    int i = blockIdx.x * 256 + threadIdx.x;
    if (i < n) {
        float v = in[i];
        __nv_bfloat16 hi = __float2bfloat16(v);
        h[i] = hi;
        l[i] = __float2bfloat16(v - __bfloat162float(hi));
    }
}

__global__ void embed2_k(const int* __restrict__ ids0, const int* __restrict__ ids1,
                         const float* __restrict__ t0, const float* __restrict__ t1,
                         float* __restrict__ out,
                         __nv_bfloat16* __restrict__ oh, __nv_bfloat16* __restrict__ ol)
{
    int z = blockIdx.y, n = blockIdx.x, d = threadIdx.x;
    const int*   ids = z ? ids1 : ids0;
    const float* tab = z ? t1   : t0;
    size_t o = ((size_t)z*NTOK + n)*Dm + d;
    float v = tab[(size_t)ids[n]*Dm + d];
    out[o] = v;
    __nv_bfloat16 hi = __float2bfloat16(v);
    oh[o] = hi;
    ol[o] = __float2bfloat16(v - __bfloat162float(hi));
}

// ================= split-bf16 tensor-core GEMM ==============================
// C[M,N] = (Ah+Al)[M,K] @ (Bh+Bl)[N,K]^T + bias   (AlBl dropped)
// Block tile 128x128, stage BK=32, 8 warps (4x2), warp tile 32x64.
// 2-stage ring (80KB smem) -> 2 CTAs/SM (launch_bounds(256,2), regs<=128).
// CVTB=false: A/B bf16 hi/lo, cp.async; wait0 -> sync -> issue(it+1) (race-free).
// CVTB=true : B raw fp32 [N, ldb] (ldb=K+1); loader converts hi/lo on store.
// TOUT==8: time-broadcast epilogue, wlast = Bf[n*ldb + K].
#define PITCH  80
#define TILEB  (128*PITCH)
#define STAGEB (4*TILEB)
#define GSMEM  (2*STAGEB)      // 81920

template<int TOUT, bool RELU, bool OUTBF16, bool CVTB>
__global__ __launch_bounds__(256, 2)
void gemm_mma(const __nv_bfloat16* __restrict__ Ah, const __nv_bfloat16* __restrict__ Al,
              int lda, size_t sA,
              const __nv_bfloat16* __restrict__ Bh16, const __nv_bfloat16* __restrict__ Bl16,
              const float* __restrict__ Bf,
              int ldb, size_t sB,
              const float* __restrict__ bias, size_t sBias,
              float* __restrict__ Cf,
              __nv_bfloat16* __restrict__ Ch, __nv_bfloat16* __restrict__ Cl,
              int ldc, size_t sC, int N, int K)
{
    extern __shared__ __align__(16) char sm[];

    int tid  = threadIdx.x;
    int wid  = tid >> 5;
    int lane = tid & 31;
    int z = blockIdx.z;
    Ah += (size_t)z * sA;  Al += (size_t)z * sA;
    if (!CVTB) { Bh16 += (size_t)z * sB; Bl16 += (size_t)z * sB; }
    bias += (size_t)z * sBias;
    if (OUTBF16) { Ch += (size_t)z * sC; Cl += (size_t)z * sC; }
    else         { Cf += (size_t)z * sC; }

    int m0 = blockIdx.y * 128;
    int n0 = blockIdx.x * 128;

    int lrow  = tid >> 1;
    int lhalf = tid & 1;
    int sdst = lrow*PITCH + lhalf*32;
    uint32_t sbase = smem_u32(sm);

    // compute mapping
    int wm = wid & 3;
    int wn = wid >> 2;
    int r8 = lane & 7, quad = lane >> 3;
    int arow = wm*32 + (quad & 1)*8 + r8;
    int aoff = (quad >> 1)*16;
    int brow = wn*64 + (quad >> 1)*8 + r8;
    int boff = (quad & 1)*16;

    float acc[2][8][4];
#pragma unroll
    for (int i = 0; i < 2; i++)
#pragma unroll
        for (int j = 0; j < 8; j++)
#pragma unroll
            for (int c = 0; c < 4; c++) acc[i][j][c] = 0.f;

    const int nst = K / 32;

    if (!CVTB) {
        // ---------- 2-stage cp.async pipeline ----------
        const __nv_bfloat16* gAh = Ah + (size_t)(m0 + lrow)*lda + lhalf*16;
        const __nv_bfloat16* gAl = Al + (size_t)(m0 + lrow)*lda + lhalf*16;
        const __nv_bfloat16* gBh = Bh16 + (size_t)(n0 + lrow)*ldb + lhalf*16;
        const __nv_bfloat16* gBl = Bl16 + (size_t)(n0 + lrow)*ldb + lhalf*16;

#define ISSUE(s) do { \
        uint32_t st_ = sbase + ((s) & 1)*STAGEB + sdst; \
        int k0_ = (s)*32; \
        CP16(st_,              gAh + k0_); CP16(st_ + 16,             gAh + k0_ + 8); \
        CP16(st_ +   TILEB,    gAl + k0_); CP16(st_ +   TILEB + 16,   gAl + k0_ + 8); \
        CP16(st_ + 2*TILEB,    gBh + k0_); CP16(st_ + 2*TILEB + 16,   gBh + k0_ + 8); \
        CP16(st_ + 3*TILEB,    gBl + k0_); CP16(st_ + 3*TILEB + 16,   gBl + k0_ + 8); \
        CP_COMMIT(); } while (0)

        ISSUE(0);

        for (int it = 0; it < nst; ++it) {
            CP_WAIT0();            // stage it landed
            __syncthreads();       // all warps done with compute(it-1) too
            if (it + 1 < nst) ISSUE(it + 1);   // other buffer: safe + overlapped

            uint32_t stb = sbase + (it & 1)*STAGEB;
            uint32_t bAh = stb;
            uint32_t bAl = stb + TILEB;
            uint32_t bBh = stb + 2*TILEB;
            uint32_t bBl = stb + 3*TILEB;
#pragma unroll
            for (int ks = 0; ks < 2; ks++) {
                int ko = ks * 32;
                uint32_t ah[2][4], al[2][4];
#pragma unroll
                for (int mi = 0; mi < 2; mi++) {
                    ldm_x4(ah[mi], bAh + (arow + mi*16)*PITCH + ko + aoff);
                    ldm_x4(al[mi], bAl + (arow + mi*16)*PITCH + ko + aoff);
                }
#pragma unroll
                for (int pj = 0; pj < 4; pj++) {
                    uint32_t bh4[4], bl4[4];
                    ldm_x4(bh4, bBh + (brow + pj*16)*PITCH + ko + boff);
                    ldm_x4(bl4, bBl + (brow + pj*16)*PITCH + ko + boff);
#pragma unroll
                    for (int mi = 0; mi < 2; mi++) {
                        mma16816(acc[mi][2*pj],   ah[mi], bh4[0], bh4[1]);
                        mma16816(acc[mi][2*pj+1], ah[mi], bh4[2], bh4[3]);
                        mma16816(acc[mi][2*pj],   al[mi], bh4[0], bh4[1]);
                        mma16816(acc[mi][2*pj+1], al[mi], bh4[2], bh4[3]);
                        mma16816(acc[mi][2*pj],   ah[mi], bl4[0], bl4[1]);
                        mma16816(acc[mi][2*pj+1], ah[mi], bl4[2], bl4[3]);
                    }
                }
            }
        }
#undef ISSUE
    } else {
        // ---------- 2-stage register path, B fp32 converted on store ----------
        int browg = min(n0 + lrow, N - 1);
        const __nv_bfloat16* gAh = Ah + (size_t)(m0 + lrow)*lda + lhalf*16;
        const __nv_bfloat16* gAl = Al + (size_t)(m0 + lrow)*lda + lhalf*16;
        const float* gB = Bf + (size_t)browg*ldb + lhalf*16;

        uint4 pa0, pa1, pa2, pa3;        // full 32B per thread for Ah and Al
        uint32_t pbh[8], pbl[8];

        auto loadstage = [&](int k0) {
            pa0 = *(const uint4*)(gAh + k0);
            pa1 = *(const uint4*)(gAh + k0 + 8);
            pa2 = *(const uint4*)(gAl + k0);
            pa3 = *(const uint4*)(gAl + k0 + 8);
#pragma unroll
            for (int j = 0; j < 8; j++) {
                float v0 = gB[k0 + 2*j];
                float v1 = gB[k0 + 2*j + 1];
                __nv_bfloat16 h0 = __float2bfloat16(v0);
                __nv_bfloat16 h1 = __float2bfloat16(v1);
                __nv_bfloat162 hp; hp.x = h0; hp.y = h1;
                __nv_bfloat162 lp;
                lp.x = __float2bfloat16(v0 - __bfloat162float(h0));
                lp.y = __float2bfloat16(v1 - __bfloat162float(h1));
                pbh[j] = *(uint32_t*)&hp;
                pbl[j] = *(uint32_t*)&lp;
            }
        };
        auto storestage = [&](int b) {
            char* stg = sm + b*STAGEB;
            *(uint4*)(stg + sdst)                = pa0;
            *(uint4*)(stg + sdst + 16)           = pa1;
            *(uint4*)(stg + TILEB + sdst)        = pa2;
            *(uint4*)(stg + TILEB + sdst + 16)   = pa3;
            *(uint4*)(stg + 2*TILEB + sdst)      = make_uint4(pbh[0],pbh[1],pbh[2],pbh[3]);
            *(uint4*)(stg + 2*TILEB + sdst + 16) = make_uint4(pbh[4],pbh[5],pbh[6],pbh[7]);
            *(uint4*)(stg + 3*TILEB + sdst)      = make_uint4(pbl[0],pbl[1],pbl[2],pbl[3]);
            *(uint4*)(stg + 3*TILEB + sdst + 16) = make_uint4(pbl[4],pbl[5],pbl[6],pbl[7]);
        };

        loadstage(0);
        storestage(0);

        for (int it = 0; it < nst; ++it) {
            int buf = it & 1;
            bool more = (it + 1) < nst;
            if (more) loadstage((it + 1) * 32);
            __syncthreads();

            uint32_t stb = sbase + buf*STAGEB;
            uint32_t bAh = stb;
            uint32_t bAl = stb + TILEB;
            uint32_t bBh = stb + 2*TILEB;
            uint32_t bBl = stb + 3*TILEB;
#pragma unroll
            for (int ks = 0; ks < 2; ks++) {
                int ko = ks * 32;
                uint32_t ah[2][4], al[2][4];
#pragma unroll
                for (int mi = 0; mi < 2; mi++) {
                    ldm_x4(ah[mi], bAh + (arow + mi*16)*PITCH + ko + aoff);
                    ldm_x4(al[mi], bAl + (arow + mi*16)*PITCH + ko + aoff);
                }
#pragma unroll
                for (int pj = 0; pj < 4; pj++) {
                    uint32_t bh4[4], bl4[4];
                    ldm_x4(bh4, bBh + (brow + pj*16)*PITCH + ko + boff);
                    ldm_x4(bl4, bBl + (brow + pj*16)*PITCH + ko + boff);
#pragma unroll
                    for (int mi = 0; mi < 2; mi++) {
                        mma16816(acc[mi][2*pj],   ah[mi], bh4[0], bh4[1]);
                        mma16816(acc[mi][2*pj+1], ah[mi], bh4[2], bh4[3]);
                        mma16816(acc[mi][2*pj],   al[mi], bh4[0], bh4[1]);
                        mma16816(acc[mi][2*pj+1], al[mi], bh4[2], bh4[3]);
                        mma16816(acc[mi][2*pj],   ah[mi], bl4[0], bl4[1]);
                        mma16816(acc[mi][2*pj+1], ah[mi], bl4[2], bl4[3]);
                    }
                }
            }

            if (more) {
                __syncthreads();
                storestage(buf ^ 1);
            }
        }
    }

    // ---- epilogue ----
    int mrow0 = m0 + wm*32 + (lane >> 2);
    int ncol0 = n0 + wn*64 + (lane & 3)*2;
#pragma unroll
    for (int mi = 0; mi < 2; mi++) {
#pragma unroll
        for (int nj = 0; nj < 8; nj++) {
            int col = ncol0 + nj*8;
            if (CVTB && col >= N) continue;
            float b0 = bias[col], b1 = bias[col + 1];
            float w0 = 0.f, w1 = 0.f;
            if (TOUT > 1) {
                w0 = Bf[(size_t)col*ldb + K];
                w1 = Bf[(size_t)(col + 1)*ldb + K];
            }
#pragma unroll
            for (int half = 0; half < 2; half++) {
                int row = mrow0 + mi*16 + half*8;
                float v0 = acc[mi][nj][2*half]     + b0;
                float v1 = acc[mi][nj][2*half + 1] + b1;
                if (RELU) { v0 = fmaxf(v0, 0.f); v1 = fmaxf(v1, 0.f); }
                if (TOUT > 1) {
#pragma unroll
                    for (int tt = 0; tt < TOUTN; tt++) {
                        float2 v; v.x = v0 + tt*w0; v.y = v1 + tt*w1;
                        *(float2*)(Cf + (size_t)(row*TOUTN + tt)*ldc + col) = v;
                    }
                } else if (OUTBF16) {
                    __nv_bfloat16 h0 = __float2bfloat16(v0);
                    __nv_bfloat16 h1 = __float2bfloat16(v1);
                    __nv_bfloat162 hp; hp.x = h0; hp.y = h1;
                    __nv_bfloat162 lp;
                    lp.x = __float2bfloat16(v0 - __bfloat162float(h0));
                    lp.y = __float2bfloat16(v1 - __bfloat162float(h1));
                    *(__nv_bfloat162*)(Ch + (size_t)row*ldc + col) = hp;
                    *(__nv_bfloat162*)(Cl + (size_t)row*ldc + col) = lp;
                } else {
                    float2 v; v.x = v0; v.y = v1;
                    *(float2*)(Cf + (size_t)row*ldc + col) = v;
                }
            }
        }
    }
}

// ================= attention (fp32 math, bf16-split output) =================
__global__ __launch_bounds__(256)
void attn_k(const float* __restrict__ qkv,
            __nv_bfloat16* __restrict__ oh, __nv_bfloat16* __restrict__ ol)
{
    int z = blockIdx.y;
    int bh = blockIdx.x;
    int b = bh / Hh, h = bh % Hh;
    __shared__ float ks[Sl][HD];
    __shared__ float vs[Sl][HD];
    int tid = threadIdx.x;
    const float* base = qkv + ((size_t)z*NTOK + (size_t)b*Sl)*(3*Dm);

    for (int e = tid; e < Sl*HD; e += 256) {
        int s = e / HD, d = e % HD;
        ks[s][d] = base[s*(3*Dm) + Dm   + h*HD + d];
        vs[s][d] = base[s*(3*Dm) + 2*Dm + h*HD + d];
    }
    __syncthreads();

    if (tid < Sl) {
        int s = tid;
        float q[HD];
#pragma unroll
        for (int d = 0; d < HD; d++)
            q[d] = base[s*(3*Dm) + h*HD + d] * 0.25f;

        float m = -1e30f, l = 0.f;
        float acc[HD];
#pragma unroll
        for (int d = 0; d < HD; d++) acc[d] = 0.f;

        for (int j = 0; j < Sl; j++) {
            float sc = 0.f;
#pragma unroll
            for (int d = 0; d < HD; d++) sc = fmaf(q[d], ks[j][d], sc);
            float nm  = fmaxf(m, sc);
            float cor = __expf(m - nm);
            float p   = __expf(sc - nm);
            l = l*cor + p;
#pragma unroll
            for (int d = 0; d < HD; d++) acc[d] = acc[d]*cor + p*vs[j][d];
            m = nm;
        }
        float inv = 1.f / l;
        size_t o = ((size_t)z*NTOK + (size_t)b*Sl + s)*Dm + h*HD;
#pragma unroll
        for (int d = 0; d < HD; d++) {
            float v = acc[d]*inv;
            __nv_bfloat16 hi = __float2bfloat16(v);
            oh[o + d] = hi;
            ol[o + d] = __float2bfloat16(v - __bfloat162float(hi));
        }
    }
}

// ========= fused residual-add + LayerNorm -> x(fp32) + xh/xl(bf16) =========
__global__ void add_ln_k(float* __restrict__ x, const float* __restrict__ r,
                         const float* __restrict__ g, const float* __restrict__ b,
                         size_t sW,
                         __nv_bfloat16* __restrict__ xh, __nv_bfloat16* __restrict__ xl)
{
    int z = blockIdx.y;
    int n = blockIdx.x, d = threadIdx.x;
    size_t tok = (size_t)z*NTOK + n;
    g += (size_t)z * sW;
    b += (size_t)z * sW;
    __shared__ float red[8];
    float v = x[tok*Dm + d] + r[tok*Dm + d];

    float s = v;
#pragma unroll
    for (int o = 16; o > 0; o >>= 1) s += __shfl_xor_sync(0xffffffffu, s, o);
    if ((d & 31) == 0) red[d >> 5] = s;
    __syncthreads();
    float mean = (red[0]+red[1]+red[2]+red[3]) * (1.f/Dm);

    float c = v - mean;
    float s2 = c*c;
#pragma unroll
    for (int o = 16; o > 0; o >>= 1) s2 += __shfl_xor_sync(0xffffffffu, s2, o);
    if ((d & 31) == 0) red[4 + (d >> 5)] = s2;
    __syncthreads();
    float var = (red[4]+red[5]+red[6]+red[7]) * (1.f/Dm);

    float y = c * rsqrtf(var + 1e-5f) * g[d] + b[d];
    x[tok*Dm + d] = y;
    __nv_bfloat16 hi = __float2bfloat16(y);
    xh[tok*Dm + d] = hi;
    xl[tok*Dm + d] = __float2bfloat16(y - __bfloat162float(hi));
}

// ---------------- sequence mean into split hcat --------------------------
__global__ void mean_k(const float* __restrict__ x,
                       __nv_bfloat16* __restrict__ oh, __nv_bfloat16* __restrict__ ol)
{
    int z = blockIdx.y;
    int b = blockIdx.x, d = threadIdx.x;
    const float* xp = x + ((size_t)z*NTOK + (size_t)b*Sl)*Dm;
    float s = 0.f;
    for (int j = 0; j < Sl; j++) s += xp[j*Dm + d];
    float v = s * (1.f/Sl);
    __nv_bfloat16 hi = __float2bfloat16(v);
    oh[b*(2*Dm) + z*Dm + d] = hi;
    ol[b*(2*Dm) + z*Dm + d] = __float2bfloat16(v - __bfloat162float(hi));
}

// ================= launcher =================
extern "C" void kernel_launch(void* const* d_in, const int* in_sizes, int n_in,
                              void* d_out, int out_size)
{
    const int*   tid_seq = (const int*)  d_in[0];
    const int*   iid_seq = (const int*)  d_in[1];
    const float* tab_emb = (const float*)d_in[2];
    const float* idx_emb = (const float*)d_in[3];
    const float* Wqkv = (const float*)d_in[4];
    const float* bqkv = (const float*)d_in[5];
    const float* Wo   = (const float*)d_in[6];
    const float* bo   = (const float*)d_in[7];
    const float* ln1g = (const float*)d_in[8];
    const float* ln1b = (const float*)d_in[9];
    const float* W1   = (const float*)d_in[10];
    const float* b1   = (const float*)d_in[11];
    const float* W2   = (const float*)d_in[12];
    const float* b2   = (const float*)d_in[13];
    const float* ln2g = (const float*)d_in[14];
    const float* ln2b = (const float*)d_in[15];
    const float* Wlin = (const float*)d_in[16];
    const float* blin = (const float*)d_in[17];
    const float* Wtab = (const float*)d_in[18];
    const float* btab = (const float*)d_in[19];
    const float* Widx = (const float*)d_in[20];
    const float* bidx = (const float*)d_in[21];

    float* out     = (float*)d_out;
    float* out_tab = out;
    float* out_idx = out + (size_t)Bz*TOUTN*TBLV;

    float *x, *qkv, *tmp;
    __nv_bfloat16 *xh, *xl, *ath, *atl, *ffh, *ffl;
    __nv_bfloat16 *hcath, *hcatl, *hh, *hl;
    __nv_bfloat16 *Wqkvh, *Wqkvl, *Woh, *Wol, *W1h, *W1l, *W2h, *W2l;
    __nv_bfloat16 *Wlinh, *Wlinl;
    cudaGetSymbolAddress((void**)&x,    g_x);
    cudaGetSymbolAddress((void**)&qkv,  g_qkv);
    cudaGetSymbolAddress((void**)&tmp,  g_tmp);
    cudaGetSymbolAddress((void**)&xh,   g_xh);
    cudaGetSymbolAddress((void**)&xl,   g_xl);
    cudaGetSymbolAddress((void**)&ath,  g_ath);
    cudaGetSymbolAddress((void**)&atl,  g_atl);
    cudaGetSymbolAddress((void**)&ffh,  g_ffh);
    cudaGetSymbolAddress((void**)&ffl,  g_ffl);
    cudaGetSymbolAddress((void**)&hcath, g_hcath);
    cudaGetSymbolAddress((void**)&hcatl, g_hcatl);
    cudaGetSymbolAddress((void**)&hh,   g_hh);
    cudaGetSymbolAddress((void**)&hl,   g_hl);
    cudaGetSymbolAddress((void**)&Wqkvh, g_Wqkvh);
    cudaGetSymbolAddress((void**)&Wqkvl, g_Wqkvl);
    cudaGetSymbolAddress((void**)&Woh,   g_Woh);
    cudaGetSymbolAddress((void**)&Wol,   g_Wol);
    cudaGetSymbolAddress((void**)&W1h,   g_W1h);
    cudaGetSymbolAddress((void**)&W1l,   g_W1l);
    cudaGetSymbolAddress((void**)&W2h,   g_W2h);
    cudaGetSymbolAddress((void**)&W2l,   g_W2l);
    cudaGetSymbolAddress((void**)&Wlinh, g_Wlinh);
    cudaGetSymbolAddress((void**)&Wlinl, g_Wlinl);

    cudaFuncSetAttribute(gemm_mma<1,false,false,false>, cudaFuncAttributeMaxDynamicSharedMemorySize, GSMEM);
    cudaFuncSetAttribute(gemm_mma<1,true, true, false>, cudaFuncAttributeMaxDynamicSharedMemorySize, GSMEM);
    cudaFuncSetAttribute(gemm_mma<TOUTN,false,false,true>, cudaFuncAttributeMaxDynamicSharedMemorySize, GSMEM);

    const int MT = NTOK / 128;  // 200
    const size_t sX   = (size_t)NTOK*Dm;
    const size_t sQKV = (size_t)NTOK*3*Dm;
    const size_t sFF  = (size_t)NTOK*DFF;

    // launches 0-3: encoder weight splits; 4: embed; 5: first qkv GEMM (ncu -s 5)
    cvt_k<<<(2*Ll*3*Dm*Dm + 255)/256, 256>>>(Wqkv, Wqkvh, Wqkvl, 2*Ll*3*Dm*Dm);
    cvt_k<<<(2*Ll*Dm*Dm   + 255)/256, 256>>>(Wo,   Woh,   Wol,   2*Ll*Dm*Dm);
    cvt_k<<<(2*Ll*DFF*Dm  + 255)/256, 256>>>(W1,   W1h,   W1l,   2*Ll*DFF*Dm);
    cvt_k<<<(2*Ll*Dm*DFF  + 255)/256, 256>>>(W2,   W2h,   W2l,   2*Ll*Dm*DFF);

    embed2_k<<<dim3(NTOK, 2), Dm>>>(tid_seq, iid_seq, tab_emb, idx_emb, x, xh, xl);

    for (int l = 0; l < Ll; l++) {
        // qkv = x @ Wqkv^T + b
        gemm_mma<1,false,false,false><<<dim3(3, MT, 2), 256, GSMEM>>>(
            xh, xl, Dm, sX,
            Wqkvh + (size_t)l*3*Dm*Dm, Wqkvl + (size_t)l*3*Dm*Dm, nullptr,
            Dm, (size_t)Ll*3*Dm*Dm,
            bqkv + (size_t)l*3*Dm, (size_t)Ll*3*Dm,
            qkv, nullptr, nullptr, 3*Dm, sQKV, 3*Dm, Dm);

        attn_k<<<dim3(Bz*Hh, 2), 256>>>(qkv, ath, atl);

        // o proj
        gemm_mma<1,false,false,false><<<dim3(1, MT, 2), 256, GSMEM>>>(
            ath, atl, Dm, sX,
            Woh + (size_t)l*Dm*Dm, Wol + (size_t)l*Dm*Dm, nullptr,
            Dm, (size_t)Ll*Dm*Dm,
            bo + (size_t)l*Dm, (size_t)Ll*Dm,
            tmp, nullptr, nullptr, Dm, sX, Dm, Dm);

        add_ln_k<<<dim3(NTOK, 2), Dm>>>(x, tmp, ln1g + (size_t)l*Dm, ln1b + (size_t)l*Dm,
                                        (size_t)Ll*Dm, xh, xl);

        // ff = relu(x @ W1^T + b1) -> bf16 hi/lo
        gemm_mma<1,true,true,false><<<dim3(DFF/128, MT, 2), 256, GSMEM>>>(
            xh, xl, Dm, sX,
            W1h + (size_t)l*DFF*Dm, W1l + (size_t)l*DFF*Dm, nullptr,
            Dm, (size_t)Ll*DFF*Dm,
            b1 + (size_t)l*DFF, (size_t)Ll*DFF,
            nullptr, ffh, ffl, DFF, sFF, DFF, Dm);

        // tmp = ff @ W2^T + b2
        gemm_mma<1,false,false,false><<<dim3(1, MT, 2), 256, GSMEM>>>(
            ffh, ffl, DFF, sFF,
            W2h + (size_t)l*Dm*DFF, W2l + (size_t)l*Dm*DFF, nullptr,
            DFF, (size_t)Ll*Dm*DFF,
            b2 + (size_t)l*Dm, (size_t)Ll*Dm,
            tmp, nullptr, nullptr, Dm, sX, Dm, DFF);

        add_ln_k<<<dim3(NTOK, 2), Dm>>>(x, tmp, ln2g + (size_t)l*Dm, ln2b + (size_t)l*Dm,
                                        (size_t)Ll*Dm, xh, xl);
    }

    mean_k<<<dim3(Bz, 2), Dm>>>(x, hcath, hcatl);

    // Wlin split (moved late to keep GEMM at launch index 5)
    cvt_k<<<(HID*2*Dm + 255)/256, 256>>>(Wlin, Wlinh, Wlinl, HID*2*Dm);

    // h = relu(hcat @ Wlin^T + blin) -> split   [128,512] K=256
    gemm_mma<1,true,true,false><<<dim3(HID/128, 1, 1), 256, GSMEM>>>(
        hcath, hcatl, 2*Dm, 0, Wlinh, Wlinl, nullptr, 2*Dm, 0, blin, 0,
        nullptr, hh, hl, HID, 0, HID, 2*Dm);

    // tab: [128,1000] + t-broadcast -> [1024,1000]  (fp32 W converted in-kernel)
    gemm_mma<TOUTN,false,false,true><<<dim3((TBLV + 127)/128, 1, 1), 256, GSMEM>>>(
        hh, hl, HID, 0, nullptr, nullptr, Wtab, HID + 1, 0, btab, 0,
        out_tab, nullptr, nullptr, TBLV, 0, TBLV, HID);

    // idx: [128,100000] + t-broadcast -> [1024,100000]
    gemm_mma<TOUTN,false,false,true><<<dim3((IDXV + 127)/128, 1, 1), 256, GSMEM>>>(
        hh, hl, HID, 0, nullptr, nullptr, Widx, HID + 1, 0, bidx, 0,
        out_idx, nullptr, nullptr, IDXV, 0, IDXV, HID);
}

// round 9
// speedup vs baseline: 1.8333x; 1.0220x over previous
#include <cuda_runtime.h>
#include <cuda_bf16.h>
#include <math.h>
#include <stdint.h>

#define Bz    128
#define Sl    200
#define Dm    128
#define Hh    8
#define HD    16
#define Ll    2
#define DFF   2048
#define HID   512
#define TBLV  1000
#define IDXV  100000
#define TOUTN 8
#define NTOK  (Bz*Sl)   // 25600

// ================= scratch (device globals) =================
__device__ float g_x   [2*NTOK*Dm];
__device__ float g_qkv [2*NTOK*3*Dm];
__device__ __nv_bfloat16 g_hcath[Bz*2*Dm], g_hcatl[Bz*2*Dm];
__device__ __nv_bfloat16 g_hh[Bz*HID],     g_hl[Bz*HID];
__device__ __nv_bfloat16 g_xh [2*NTOK*Dm];
__device__ __nv_bfloat16 g_xl [2*NTOK*Dm];
__device__ __nv_bfloat16 g_ath[2*NTOK*Dm];
__device__ __nv_bfloat16 g_atl[2*NTOK*Dm];
__device__ __nv_bfloat16 g_ffh[(size_t)2*NTOK*DFF];
__device__ __nv_bfloat16 g_ffl[(size_t)2*NTOK*DFF];
__device__ __nv_bfloat16 g_Wqkvh[2*Ll*3*Dm*Dm], g_Wqkvl[2*Ll*3*Dm*Dm];
__device__ __nv_bfloat16 g_Woh  [2*Ll*Dm*Dm],   g_Wol  [2*Ll*Dm*Dm];
__device__ __nv_bfloat16 g_W1h  [2*Ll*DFF*Dm],  g_W1l  [2*Ll*DFF*Dm];
__device__ __nv_bfloat16 g_W2h  [2*Ll*Dm*DFF],  g_W2l  [2*Ll*Dm*DFF];
__device__ __nv_bfloat16 g_Wlinh[HID*2*Dm],     g_Wlinl[HID*2*Dm];

// ================= asm helpers (baseline PTX only) ==========
__device__ __forceinline__ uint32_t smem_u32(const void* p) {
    uint32_t a;
    asm("{ .reg .u64 t; cvta.to.shared.u64 t, %1; cvt.u32.u64 %0, t; }"
        : "=r"(a) : "l"(p));
    return a;
}
__device__ __forceinline__ void ldm_x4(uint32_t* r, uint32_t addr) {
    asm volatile("ldmatrix.sync.aligned.m8n8.x4.shared.b16 {%0,%1,%2,%3}, [%4];"
        : "=r"(r[0]), "=r"(r[1]), "=r"(r[2]), "=r"(r[3]) : "r"(addr));
}
__device__ __forceinline__ void mma16816(float* c, const uint32_t* a,
                                         uint32_t b0, uint32_t b1) {
    asm volatile("mma.sync.aligned.m16n8k16.row.col.f32.bf16.bf16.f32 "
        "{%0,%1,%2,%3}, {%4,%5,%6,%7}, {%8,%9}, {%0,%1,%2,%3};"
        : "+f"(c[0]), "+f"(c[1]), "+f"(c[2]), "+f"(c[3])
        : "r"(a[0]), "r"(a[1]), "r"(a[2]), "r"(a[3]), "r"(b0), "r"(b1));
}
#define CP16(dst, src) \
    asm volatile("cp.async.cg.shared.global [%0], [%1], 16;" :: "r"(dst), "l"(src))
#define CP_COMMIT() asm volatile("cp.async.commit_group;" ::: "memory")
#define CP_WAIT0()  asm volatile("cp.async.wait_group 0;" ::: "memory")

// ================= small utility kernels =================
__global__ void cvt_k(const float* __restrict__ in, __nv_bfloat16* __restrict__ h,
                      __nv_bfloat16* __restrict__ l, int n)
{
    int i = blockIdx.x * 256 + threadIdx.x;
    if (i < n) {
        float v = in[i];
        __nv_bfloat16 hi = __float2bfloat16(v);
        h[i] = hi;
        l[i] = __float2bfloat16(v - __bfloat162float(hi));
    }
}

__global__ void embed2_k(const int* __restrict__ ids0, const int* __restrict__ ids1,
                         const float* __restrict__ t0, const float* __restrict__ t1,
                         float* __restrict__ out,
                         __nv_bfloat16* __restrict__ oh, __nv_bfloat16* __restrict__ ol)
{
    int z = blockIdx.y, n = blockIdx.x, d = threadIdx.x;
    const int*   ids = z ? ids1 : ids0;
    const float* tab = z ? t1   : t0;
    size_t o = ((size_t)z*NTOK + n)*Dm + d;
    float v = tab[(size_t)ids[n]*Dm + d];
    out[o] = v;
    __nv_bfloat16 hi = __float2bfloat16(v);
    oh[o] = hi;
    ol[o] = __float2bfloat16(v - __bfloat162float(hi));
}

// ================= split-bf16 tensor-core GEMM ==============================
// C[M,N] = (Ah+Al)[M,K] @ (Bh+Bl)[N,K]^T + bias   (AlBl dropped)
// Block tile 128x128, stage BK=32, 8 warps (4x2), warp tile 32x64.
// 2-stage ring (80KB smem) -> 2 CTAs/SM.
// CVTB : B raw fp32 [N, ldb] (ldb=K+1); loader converts hi/lo on store.
// TOUT==8: time-broadcast epilogue, wlast = Bf[n*ldb + K].
// LNF  : requires N==128 (one tile = full row). Epilogue does
//        x = LN(x + acc + bias) with gamma/beta; writes Cf=x, Ch/Cl=x hi/lo.
#define PITCH  80
#define TILEB  (128*PITCH)
#define STAGEB (4*TILEB)
#define GSMEM  (2*STAGEB)      // 81920

template<int TOUT, bool RELU, bool OUTBF16, bool CVTB, bool LNF>
__global__ __launch_bounds__(256, 2)
void gemm_mma(const __nv_bfloat16* __restrict__ Ah, const __nv_bfloat16* __restrict__ Al,
              int lda, size_t sA,
              const __nv_bfloat16* __restrict__ Bh16, const __nv_bfloat16* __restrict__ Bl16,
              const float* __restrict__ Bf,
              int ldb, size_t sB,
              const float* __restrict__ bias, size_t sBias,
              const float* __restrict__ gam, const float* __restrict__ bet,
              float* __restrict__ Cf,
              __nv_bfloat16* __restrict__ Ch, __nv_bfloat16* __restrict__ Cl,
              int ldc, size_t sC, int N, int K)
{
    extern __shared__ __align__(16) char sm[];

    int tid  = threadIdx.x;
    int wid  = tid >> 5;
    int lane = tid & 31;
    int z = blockIdx.z;
    Ah += (size_t)z * sA;  Al += (size_t)z * sA;
    if (!CVTB) { Bh16 += (size_t)z * sB; Bl16 += (size_t)z * sB; }
    bias += (size_t)z * sBias;
    if (LNF) { gam += (size_t)z * sBias; bet += (size_t)z * sBias; }
    if (LNF)         { Cf += (size_t)z * sC; Ch += (size_t)z * sC; Cl += (size_t)z * sC; }
    else if (OUTBF16){ Ch += (size_t)z * sC; Cl += (size_t)z * sC; }
    else             { Cf += (size_t)z * sC; }

    int m0 = blockIdx.y * 128;
    int n0 = blockIdx.x * 128;

    int lrow  = tid >> 1;
    int lhalf = tid & 1;
    int sdst = lrow*PITCH + lhalf*32;
    uint32_t sbase = smem_u32(sm);

    // compute mapping
    int wm = wid & 3;
    int wn = wid >> 2;
    int r8 = lane & 7, quad = lane >> 3;
    int arow = wm*32 + (quad & 1)*8 + r8;
    int aoff = (quad >> 1)*16;
    int brow = wn*64 + (quad >> 1)*8 + r8;
    int boff = (quad & 1)*16;

    float acc[2][8][4];
#pragma unroll
    for (int i = 0; i < 2; i++)
#pragma unroll
        for (int j = 0; j < 8; j++)
#pragma unroll
            for (int c = 0; c < 4; c++) acc[i][j][c] = 0.f;

    const int nst = K / 32;

    if (!CVTB) {
        const __nv_bfloat16* gAh = Ah + (size_t)(m0 + lrow)*lda + lhalf*16;
        const __nv_bfloat16* gAl = Al + (size_t)(m0 + lrow)*lda + lhalf*16;
        const __nv_bfloat16* gBh = Bh16 + (size_t)(n0 + lrow)*ldb + lhalf*16;
        const __nv_bfloat16* gBl = Bl16 + (size_t)(n0 + lrow)*ldb + lhalf*16;

#define ISSUE(s) do { \
        uint32_t st_ = sbase + ((s) & 1)*STAGEB + sdst; \
        int k0_ = (s)*32; \
        CP16(st_,              gAh + k0_); CP16(st_ + 16,             gAh + k0_ + 8); \
        CP16(st_ +   TILEB,    gAl + k0_); CP16(st_ +   TILEB + 16,   gAl + k0_ + 8); \
        CP16(st_ + 2*TILEB,    gBh + k0_); CP16(st_ + 2*TILEB + 16,   gBh + k0_ + 8); \
        CP16(st_ + 3*TILEB,    gBl + k0_); CP16(st_ + 3*TILEB + 16,   gBl + k0_ + 8); \
        CP_COMMIT(); } while (0)

        ISSUE(0);

        for (int it = 0; it < nst; ++it) {
            CP_WAIT0();
            __syncthreads();
            if (it + 1 < nst) ISSUE(it + 1);

            uint32_t stb = sbase + (it & 1)*STAGEB;
            uint32_t bAh = stb;
            uint32_t bAl = stb + TILEB;
            uint32_t bBh = stb + 2*TILEB;
            uint32_t bBl = stb + 3*TILEB;
#pragma unroll
            for (int ks = 0; ks < 2; ks++) {
                int ko = ks * 32;
                uint32_t ah[2][4], al[2][4];
#pragma unroll
                for (int mi = 0; mi < 2; mi++) {
                    ldm_x4(ah[mi], bAh + (arow + mi*16)*PITCH + ko + aoff);
                    ldm_x4(al[mi], bAl + (arow + mi*16)*PITCH + ko + aoff);
                }
#pragma unroll
                for (int pj = 0; pj < 4; pj++) {
                    uint32_t bh4[4], bl4[4];
                    ldm_x4(bh4, bBh + (brow + pj*16)*PITCH + ko + boff);
                    ldm_x4(bl4, bBl + (brow + pj*16)*PITCH + ko + boff);
#pragma unroll
                    for (int mi = 0; mi < 2; mi++) {
                        mma16816(acc[mi][2*pj],   ah[mi], bh4[0], bh4[1]);
                        mma16816(acc[mi][2*pj+1], ah[mi], bh4[2], bh4[3]);
                        mma16816(acc[mi][2*pj],   al[mi], bh4[0], bh4[1]);
                        mma16816(acc[mi][2*pj+1], al[mi], bh4[2], bh4[3]);
                        mma16816(acc[mi][2*pj],   ah[mi], bl4[0], bl4[1]);
                        mma16816(acc[mi][2*pj+1], ah[mi], bl4[2], bl4[3]);
                    }
                }
            }
        }
#undef ISSUE
    } else {
        int browg = min(n0 + lrow, N - 1);
        const __nv_bfloat16* gAh = Ah + (size_t)(m0 + lrow)*lda + lhalf*16;
        const __nv_bfloat16* gAl = Al + (size_t)(m0 + lrow)*lda + lhalf*16;
        const float* gB = Bf + (size_t)browg*ldb + lhalf*16;

        uint4 pa0, pa1, pa2, pa3;
        uint32_t pbh[8], pbl[8];

        auto loadstage = [&](int k0) {
            pa0 = *(const uint4*)(gAh + k0);
            pa1 = *(const uint4*)(gAh + k0 + 8);
            pa2 = *(const uint4*)(gAl + k0);
            pa3 = *(const uint4*)(gAl + k0 + 8);
#pragma unroll
            for (int j = 0; j < 8; j++) {
                float v0 = gB[k0 + 2*j];
                float v1 = gB[k0 + 2*j + 1];
                __nv_bfloat16 h0 = __float2bfloat16(v0);
                __nv_bfloat16 h1 = __float2bfloat16(v1);
                __nv_bfloat162 hp; hp.x = h0; hp.y = h1;
                __nv_bfloat162 lp;
                lp.x = __float2bfloat16(v0 - __bfloat162float(h0));
                lp.y = __float2bfloat16(v1 - __bfloat162float(h1));
                pbh[j] = *(uint32_t*)&hp;
                pbl[j] = *(uint32_t*)&lp;
            }
        };
        auto storestage = [&](int b) {
            char* stg = sm + b*STAGEB;
            *(uint4*)(stg + sdst)                = pa0;
            *(uint4*)(stg + sdst + 16)           = pa1;
            *(uint4*)(stg + TILEB + sdst)        = pa2;
            *(uint4*)(stg + TILEB + sdst + 16)   = pa3;
            *(uint4*)(stg + 2*TILEB + sdst)      = make_uint4(pbh[0],pbh[1],pbh[2],pbh[3]);
            *(uint4*)(stg + 2*TILEB + sdst + 16) = make_uint4(pbh[4],pbh[5],pbh[6],pbh[7]);
            *(uint4*)(stg + 3*TILEB + sdst)      = make_uint4(pbl[0],pbl[1],pbl[2],pbl[3]);
            *(uint4*)(stg + 3*TILEB + sdst + 16) = make_uint4(pbl[4],pbl[5],pbl[6],pbl[7]);
        };

        loadstage(0);
        storestage(0);

        for (int it = 0; it < nst; ++it) {
            int buf = it & 1;
            bool more = (it + 1) < nst;
            if (more) loadstage((it + 1) * 32);
            __syncthreads();

            uint32_t stb = sbase + buf*STAGEB;
            uint32_t bAh = stb;
            uint32_t bAl = stb + TILEB;
            uint32_t bBh = stb + 2*TILEB;
            uint32_t bBl = stb + 3*TILEB;
#pragma unroll
            for (int ks = 0; ks < 2; ks++) {
                int ko = ks * 32;
                uint32_t ah[2][4], al[2][4];
#pragma unroll
                for (int mi = 0; mi < 2; mi++) {
                    ldm_x4(ah[mi], bAh + (arow + mi*16)*PITCH + ko + aoff);
                    ldm_x4(al[mi], bAl + (arow + mi*16)*PITCH + ko + aoff);
                }
#pragma unroll
                for (int pj = 0; pj < 4; pj++) {
                    uint32_t bh4[4], bl4[4];
                    ldm_x4(bh4, bBh + (brow + pj*16)*PITCH + ko + boff);
                    ldm_x4(bl4, bBl + (brow + pj*16)*PITCH + ko + boff);
#pragma unroll
                    for (int mi = 0; mi < 2; mi++) {
                        mma16816(acc[mi][2*pj],   ah[mi], bh4[0], bh4[1]);
                        mma16816(acc[mi][2*pj+1], ah[mi], bh4[2], bh4[3]);
                        mma16816(acc[mi][2*pj],   al[mi], bh4[0], bh4[1]);
                        mma16816(acc[mi][2*pj+1], al[mi], bh4[2], bh4[3]);
                        mma16816(acc[mi][2*pj],   ah[mi], bl4[0], bl4[1]);
                        mma16816(acc[mi][2*pj+1], ah[mi], bl4[2], bl4[3]);
                    }
                }
            }

            if (more) {
                __syncthreads();
                storestage(buf ^ 1);
            }
        }
    }

    // ---- epilogue ----
    int mrow0 = m0 + wm*32 + (lane >> 2);
    int ncol0 = n0 + wn*64 + (lane & 3)*2;

    if (LNF) {
        // full row in-block: residual + LayerNorm fused
        __syncthreads();                 // stage smem now reusable
        float* red = (float*)sm;         // [128 rows][8 partials][2]
        int rbase = wm*32 + (lane >> 5 == 0 ? (lane >> 2) : (lane >> 2)); // lane>>2
        rbase = wm*32 + (lane >> 2);
        int pcol = wn*4 + (lane & 3);

#pragma unroll
        for (int mi = 0; mi < 2; mi++)
#pragma unroll
        for (int half = 0; half < 2; half++) {
            int row = rbase + mi*16 + half*8;
            int grow = m0 + row;
            float s = 0.f, s2 = 0.f;
#pragma unroll
            for (int nj = 0; nj < 8; nj++) {
                int col = (lane & 3)*2 + wn*64 + nj*8;
                float2 res = *(const float2*)(Cf + (size_t)grow*ldc + col);
                float t0 = acc[mi][nj][2*half]     + bias[col]     + res.x;
                float t1 = acc[mi][nj][2*half + 1] + bias[col + 1] + res.y;
                acc[mi][nj][2*half]     = t0;
                acc[mi][nj][2*half + 1] = t1;
                s  += t0 + t1;
                s2 += t0*t0 + t1*t1;
            }
            red[(row*8 + pcol)*2]     = s;
            red[(row*8 + pcol)*2 + 1] = s2;
        }
        __syncthreads();

#pragma unroll
        for (int mi = 0; mi < 2; mi++)
#pragma unroll
        for (int half = 0; half < 2; half++) {
            int row = rbase + mi*16 + half*8;
            int grow = m0 + row;
            float s = 0.f, s2 = 0.f;
#pragma unroll
            for (int p = 0; p < 8; p++) {
                s  += red[(row*8 + p)*2];
                s2 += red[(row*8 + p)*2 + 1];
            }
            float mean = s * (1.f/128.f);
            float var  = s2 * (1.f/128.f) - mean*mean;
            float inv  = rsqrtf(var + 1e-5f);
#pragma unroll
            for (int nj = 0; nj < 8; nj++) {
                int col = (lane & 3)*2 + wn*64 + nj*8;
                float t0 = acc[mi][nj][2*half];
                float t1 = acc[mi][nj][2*half + 1];
                float y0 = (t0 - mean)*inv*gam[col]     + bet[col];
                float y1 = (t1 - mean)*inv*gam[col + 1] + bet[col + 1];
                float2 yv; yv.x = y0; yv.y = y1;
                *(float2*)(Cf + (size_t)grow*ldc + col) = yv;
                __nv_bfloat16 h0 = __float2bfloat16(y0);
                __nv_bfloat16 h1 = __float2bfloat16(y1);
                __nv_bfloat162 hp; hp.x = h0; hp.y = h1;
                __nv_bfloat162 lp;
                lp.x = __float2bfloat16(y0 - __bfloat162float(h0));
                lp.y = __float2bfloat16(y1 - __bfloat162float(h1));
                *(__nv_bfloat162*)(Ch + (size_t)grow*ldc + col) = hp;
                *(__nv_bfloat162*)(Cl + (size_t)grow*ldc + col) = lp;
            }
        }
        return;
    }

#pragma unroll
    for (int mi = 0; mi < 2; mi++) {
#pragma unroll
        for (int nj = 0; nj < 8; nj++) {
            int col = ncol0 + nj*8;
            if (CVTB && col >= N) continue;
            float b0 = bias[col], b1 = bias[col + 1];
            float w0 = 0.f, w1 = 0.f;
            if (TOUT > 1) {
                w0 = Bf[(size_t)col*ldb + K];
                w1 = Bf[(size_t)(col + 1)*ldb + K];
            }
#pragma unroll
            for (int half = 0; half < 2; half++) {
                int row = mrow0 + mi*16 + half*8;
                float v0 = acc[mi][nj][2*half]     + b0;
                float v1 = acc[mi][nj][2*half + 1] + b1;
                if (RELU) { v0 = fmaxf(v0, 0.f); v1 = fmaxf(v1, 0.f); }
                if (TOUT > 1) {
#pragma unroll
                    for (int tt = 0; tt < TOUTN; tt++) {
                        float2 v; v.x = v0 + tt*w0; v.y = v1 + tt*w1;
                        *(float2*)(Cf + (size_t)(row*TOUTN + tt)*ldc + col) = v;
                    }
                } else if (OUTBF16) {
                    __nv_bfloat16 h0 = __float2bfloat16(v0);
                    __nv_bfloat16 h1 = __float2bfloat16(v1);
                    __nv_bfloat162 hp; hp.x = h0; hp.y = h1;
                    __nv_bfloat162 lp;
                    lp.x = __float2bfloat16(v0 - __bfloat162float(h0));
                    lp.y = __float2bfloat16(v1 - __bfloat162float(h1));
                    *(__nv_bfloat162*)(Ch + (size_t)row*ldc + col) = hp;
                    *(__nv_bfloat162*)(Cl + (size_t)row*ldc + col) = lp;
                } else {
                    float2 v; v.x = v0; v.y = v1;
                    *(float2*)(Cf + (size_t)row*ldc + col) = v;
                }
            }
        }
    }
}

// ================= attention (fp32 math, bf16-split output) =================
__global__ __launch_bounds__(256)
void attn_k(const float* __restrict__ qkv,
            __nv_bfloat16* __restrict__ oh, __nv_bfloat16* __restrict__ ol)
{
    int z = blockIdx.y;
    int bh = blockIdx.x;
    int b = bh / Hh, h = bh % Hh;
    __shared__ float ks[Sl][HD];
    __shared__ float vs[Sl][HD];
    int tid = threadIdx.x;
    const float* base = qkv + ((size_t)z*NTOK + (size_t)b*Sl)*(3*Dm);

    for (int e = tid; e < Sl*HD; e += 256) {
        int s = e / HD, d = e % HD;
        ks[s][d] = base[s*(3*Dm) + Dm   + h*HD + d];
        vs[s][d] = base[s*(3*Dm) + 2*Dm + h*HD + d];
    }
    __syncthreads();

    if (tid < Sl) {
        int s = tid;
        float q[HD];
#pragma unroll
        for (int d = 0; d < HD; d++)
            q[d] = base[s*(3*Dm) + h*HD + d] * 0.25f;

        float m = -1e30f, l = 0.f;
        float acc[HD];
#pragma unroll
        for (int d = 0; d < HD; d++) acc[d] = 0.f;

        for (int j = 0; j < Sl; j++) {
            float sc = 0.f;
#pragma unroll
            for (int d = 0; d < HD; d++) sc = fmaf(q[d], ks[j][d], sc);
            float nm  = fmaxf(m, sc);
            float cor = __expf(m - nm);
            float p   = __expf(sc - nm);
            l = l*cor + p;
#pragma unroll
            for (int d = 0; d < HD; d++) acc[d] = acc[d]*cor + p*vs[j][d];
            m = nm;
        }
        float inv = 1.f / l;
        size_t o = ((size_t)z*NTOK + (size_t)b*Sl + s)*Dm + h*HD;
#pragma unroll
        for (int d = 0; d < HD; d++) {
            float v = acc[d]*inv;
            __nv_bfloat16 hi = __float2bfloat16(v);
            oh[o + d] = hi;
            ol[o + d] = __float2bfloat16(v - __bfloat162float(hi));
        }
    }
}

// ---------------- sequence mean into split hcat --------------------------
__global__ void mean_k(const float* __restrict__ x,
                       __nv_bfloat16* __restrict__ oh, __nv_bfloat16* __restrict__ ol)
{
    int z = blockIdx.y;
    int b = blockIdx.x, d = threadIdx.x;
    const float* xp = x + ((size_t)z*NTOK + (size_t)b*Sl)*Dm;
    float s = 0.f;
    for (int j = 0; j < Sl; j++) s += xp[j*Dm + d];
    float v = s * (1.f/Sl);
    __nv_bfloat16 hi = __float2bfloat16(v);
    oh[b*(2*Dm) + z*Dm + d] = hi;
    ol[b*(2*Dm) + z*Dm + d] = __float2bfloat16(v - __bfloat162float(hi));
}

// ================= launcher =================
extern "C" void kernel_launch(void* const* d_in, const int* in_sizes, int n_in,
                              void* d_out, int out_size)
{
    const int*   tid_seq = (const int*)  d_in[0];
    const int*   iid_seq = (const int*)  d_in[1];
    const float* tab_emb = (const float*)d_in[2];
    const float* idx_emb = (const float*)d_in[3];
    const float* Wqkv = (const float*)d_in[4];
    const float* bqkv = (const float*)d_in[5];
    const float* Wo   = (const float*)d_in[6];
    const float* bo   = (const float*)d_in[7];
    const float* ln1g = (const float*)d_in[8];
    const float* ln1b = (const float*)d_in[9];
    const float* W1   = (const float*)d_in[10];
    const float* b1   = (const float*)d_in[11];
    const float* W2   = (const float*)d_in[12];
    const float* b2   = (const float*)d_in[13];
    const float* ln2g = (const float*)d_in[14];
    const float* ln2b = (const float*)d_in[15];
    const float* Wlin = (const float*)d_in[16];
    const float* blin = (const float*)d_in[17];
    const float* Wtab = (const float*)d_in[18];
    const float* btab = (const float*)d_in[19];
    const float* Widx = (const float*)d_in[20];
    const float* bidx = (const float*)d_in[21];

    float* out     = (float*)d_out;
    float* out_tab = out;
    float* out_idx = out + (size_t)Bz*TOUTN*TBLV;

    float *x, *qkv;
    __nv_bfloat16 *xh, *xl, *ath, *atl, *ffh, *ffl;
    __nv_bfloat16 *hcath, *hcatl, *hh, *hl;
    __nv_bfloat16 *Wqkvh, *Wqkvl, *Woh, *Wol, *W1h, *W1l, *W2h, *W2l;
    __nv_bfloat16 *Wlinh, *Wlinl;
    cudaGetSymbolAddress((void**)&x,    g_x);
    cudaGetSymbolAddress((void**)&qkv,  g_qkv);
    cudaGetSymbolAddress((void**)&xh,   g_xh);
    cudaGetSymbolAddress((void**)&xl,   g_xl);
    cudaGetSymbolAddress((void**)&ath,  g_ath);
    cudaGetSymbolAddress((void**)&atl,  g_atl);
    cudaGetSymbolAddress((void**)&ffh,  g_ffh);
    cudaGetSymbolAddress((void**)&ffl,  g_ffl);
    cudaGetSymbolAddress((void**)&hcath, g_hcath);
    cudaGetSymbolAddress((void**)&hcatl, g_hcatl);
    cudaGetSymbolAddress((void**)&hh,   g_hh);
    cudaGetSymbolAddress((void**)&hl,   g_hl);
    cudaGetSymbolAddress((void**)&Wqkvh, g_Wqkvh);
    cudaGetSymbolAddress((void**)&Wqkvl, g_Wqkvl);
    cudaGetSymbolAddress((void**)&Woh,   g_Woh);
    cudaGetSymbolAddress((void**)&Wol,   g_Wol);
    cudaGetSymbolAddress((void**)&W1h,   g_W1h);
    cudaGetSymbolAddress((void**)&W1l,   g_W1l);
    cudaGetSymbolAddress((void**)&W2h,   g_W2h);
    cudaGetSymbolAddress((void**)&W2l,   g_W2l);
    cudaGetSymbolAddress((void**)&Wlinh, g_Wlinh);
    cudaGetSymbolAddress((void**)&Wlinl, g_Wlinl);

    cudaFuncSetAttribute(gemm_mma<1,false,false,false,false>, cudaFuncAttributeMaxDynamicSharedMemorySize, GSMEM);
    cudaFuncSetAttribute(gemm_mma<1,false,false,false,true >, cudaFuncAttributeMaxDynamicSharedMemorySize, GSMEM);
    cudaFuncSetAttribute(gemm_mma<1,true, true, false,false>, cudaFuncAttributeMaxDynamicSharedMemorySize, GSMEM);
    cudaFuncSetAttribute(gemm_mma<TOUTN,false,false,true,false>, cudaFuncAttributeMaxDynamicSharedMemorySize, GSMEM);

    const int MT = NTOK / 128;  // 200
    const size_t sX   = (size_t)NTOK*Dm;
    const size_t sQKV = (size_t)NTOK*3*Dm;
    const size_t sFF  = (size_t)NTOK*DFF;

    cvt_k<<<(2*Ll*3*Dm*Dm + 255)/256, 256>>>(Wqkv, Wqkvh, Wqkvl, 2*Ll*3*Dm*Dm);
    cvt_k<<<(2*Ll*Dm*Dm   + 255)/256, 256>>>(Wo,   Woh,   Wol,   2*Ll*Dm*Dm);
    cvt_k<<<(2*Ll*DFF*Dm  + 255)/256, 256>>>(W1,   W1h,   W1l,   2*Ll*DFF*Dm);
    cvt_k<<<(2*Ll*Dm*DFF  + 255)/256, 256>>>(W2,   W2h,   W2l,   2*Ll*Dm*DFF);

    embed2_k<<<dim3(NTOK, 2), Dm>>>(tid_seq, iid_seq, tab_emb, idx_emb, x, xh, xl);

    for (int l = 0; l < Ll; l++) {
        // qkv = x @ Wqkv^T + b
        gemm_mma<1,false,false,false,false><<<dim3(3, MT, 2), 256, GSMEM>>>(
            xh, xl, Dm, sX,
            Wqkvh + (size_t)l*3*Dm*Dm, Wqkvl + (size_t)l*3*Dm*Dm, nullptr,
            Dm, (size_t)Ll*3*Dm*Dm,
            bqkv + (size_t)l*3*Dm, (size_t)Ll*3*Dm, nullptr, nullptr,
            qkv, nullptr, nullptr, 3*Dm, sQKV, 3*Dm, Dm);

        attn_k<<<dim3(Bz*Hh, 2), 256>>>(qkv, ath, atl);

        // x = LN(x + att @ Wo^T + bo)  -- fused epilogue
        gemm_mma<1,false,false,false,true><<<dim3(1, MT, 2), 256, GSMEM>>>(
            ath, atl, Dm, sX,
            Woh + (size_t)l*Dm*Dm, Wol + (size_t)l*Dm*Dm, nullptr,
            Dm, (size_t)Ll*Dm*Dm,
            bo + (size_t)l*Dm, (size_t)Ll*Dm,
            ln1g + (size_t)l*Dm, ln1b + (size_t)l*Dm,
            x, xh, xl, Dm, sX, Dm, Dm);

        // ff = relu(x @ W1^T + b1) -> bf16 hi/lo
        gemm_mma<1,true,true,false,false><<<dim3(DFF/128, MT, 2), 256, GSMEM>>>(
            xh, xl, Dm, sX,
            W1h + (size_t)l*DFF*Dm, W1l + (size_t)l*DFF*Dm, nullptr,
            Dm, (size_t)Ll*DFF*Dm,
            b1 + (size_t)l*DFF, (size_t)Ll*DFF, nullptr, nullptr,
            nullptr, ffh, ffl, DFF, sFF, DFF, Dm);

        // x = LN(x + ff @ W2^T + b2)  -- fused epilogue
        gemm_mma<1,false,false,false,true><<<dim3(1, MT, 2), 256, GSMEM>>>(
            ffh, ffl, DFF, sFF,
            W2h + (size_t)l*Dm*DFF, W2l + (size_t)l*Dm*DFF, nullptr,
            DFF, (size_t)Ll*Dm*DFF,
            b2 + (size_t)l*Dm, (size_t)Ll*Dm,
            ln2g + (size_t)l*Dm, ln2b + (size_t)l*Dm,
            x, xh, xl, Dm, sX, Dm, DFF);
    }

    mean_k<<<dim3(Bz, 2), Dm>>>(x, hcath, hcatl);

    cvt_k<<<(HID*2*Dm + 255)/256, 256>>>(Wlin, Wlinh, Wlinl, HID*2*Dm);

    // h = relu(hcat @ Wlin^T + blin) -> split   [128,512] K=256
    gemm_mma<1,true,true,false,false><<<dim3(HID/128, 1, 1), 256, GSMEM>>>(
        hcath, hcatl, 2*Dm, 0, Wlinh, Wlinl, nullptr, 2*Dm, 0, blin, 0,
        nullptr, nullptr,
        nullptr, hh, hl, HID, 0, HID, 2*Dm);

    // tab: [128,1000] + t-broadcast -> [1024,1000]
    gemm_mma<TOUTN,false,false,true,false><<<dim3((TBLV + 127)/128, 1, 1), 256, GSMEM>>>(
        hh, hl, HID, 0, nullptr, nullptr, Wtab, HID + 1, 0, btab, 0,
        nullptr, nullptr,
        out_tab, nullptr, nullptr, TBLV, 0, TBLV, HID);

    // idx: [128,100000] + t-broadcast -> [1024,100000]
    gemm_mma<TOUTN,false,false,true,false><<<dim3((IDXV + 127)/128, 1, 1), 256, GSMEM>>>(
        hh, hl, HID, 0, nullptr, nullptr, Widx, HID + 1, 0, bidx, 0,
        nullptr, nullptr,
        out_idx, nullptr, nullptr, IDXV, 0, IDXV, HID);
}